// round 12
// baseline (speedup 1.0000x reference)
#include <cuda_runtime.h>
#include <math.h>
#include <stdint.h>

// Fixed problem shape (verified R1: x[8192,4096], W[4096,4096])
#define K_IN 4096
#define NROW 8192
#define FOUT 4096

#define BM 128
#define BN 128
#define BKB 32                // K bytes per stage (32 int8)
#define NCH (K_IN / BKB)      // 128
#define MT (NROW / BM)        // 64
#define NT (FOUT / BN)        // 32
#define MAT32B (BM * 32)      // 4096 B per matrix per stage; 2*4*MAT32B = 32 KB
#define INV254 (1.f / 254.f)

// 32B-row swizzle: 16B-group id = 2*row + (c16 ^ ((row>>2)&1)) -> conflict-free
#define SWZ32(row, c16) ((((c16) ^ (((row) >> 2) & 1))) << 4)

// ---------------- device scratch ----------------
__device__ int8_t g_Ad[(size_t)NROW * (3 * K_IN)];  // [X1 | X2 | X3] per row
__device__ int8_t g_Bq[(size_t)FOUT * K_IN];        // weight codes m
__device__ float g_G[(size_t)NROW * FOUT];
__device__ float g_sn[NROW];                        // per-row scale s_n
__device__ unsigned int g_maxbits;
__device__ float g_scale;
__device__ float g_psum2[MT][FOUT];                 // per-row-block partial sums
__device__ float g_psq2[MT][FOUT];
__device__ float g_mean[FOUT];
__device__ float g_rstd[FOUT];

// ---------------- helpers (sm_80-era PTX: legal at compute_100) ----------------
__device__ __forceinline__ uint32_t smem_u32(const void* p) {
    return (uint32_t)__cvta_generic_to_shared(p);
}
#define CP_ASYNC16(dst, src) \
    asm volatile("cp.async.cg.shared.global [%0], [%1], 16;" :: "r"(dst), "l"(src) : "memory")
#define CP_COMMIT() asm volatile("cp.async.commit_group;" ::: "memory")
#define CP_WAIT1()  asm volatile("cp.async.wait_group 1;" ::: "memory")
#define CP_WAIT0()  asm volatile("cp.async.wait_group 0;" ::: "memory")

__device__ __forceinline__ void ldm_x4(uint32_t* r, uint32_t addr) {
    asm volatile("ldmatrix.sync.aligned.m8n8.x4.shared.b16 {%0,%1,%2,%3}, [%4];"
                 : "=r"(r[0]), "=r"(r[1]), "=r"(r[2]), "=r"(r[3]) : "r"(addr));
}
__device__ __forceinline__ void imma(int* d, const uint32_t* a, uint32_t b0, uint32_t b1) {
    asm volatile(
        "mma.sync.aligned.m16n8k32.row.col.s32.s8.s8.s32 "
        "{%0,%1,%2,%3}, {%4,%5,%6,%7}, {%8,%9}, {%0,%1,%2,%3};"
        : "+r"(d[0]), "+r"(d[1]), "+r"(d[2]), "+r"(d[3])
        : "r"(a[0]), "r"(a[1]), "r"(a[2]), "r"(a[3]), "r"(b0), "r"(b1));
}

// ---------------- small kernels ----------------
__global__ void init_kernel() { if (threadIdx.x == 0) g_maxbits = 0u; }

__global__ void maxabs_kernel(const float* __restrict__ W, int n) {
    float m = 0.f;
    for (int i = blockIdx.x * blockDim.x + threadIdx.x; i < n;
         i += gridDim.x * blockDim.x)
        m = fmaxf(m, fabsf(W[i]));
    #pragma unroll
    for (int o = 16; o > 0; o >>= 1)
        m = fmaxf(m, __shfl_xor_sync(0xffffffffu, m, o));
    if ((threadIdx.x & 31) == 0)
        atomicMax(&g_maxbits, __float_as_uint(m));
}

__global__ void scale_kernel(const int* __restrict__ wbits) {
    float nf = (float)((1 << ((*wbits) - 1)) - 1);
    g_scale = __fdiv_rn(__uint_as_float(g_maxbits), nf);
}

// W -> integer codes m (int8)
__global__ void quantm_kernel(const float* __restrict__ W,
                              const int* __restrict__ wbits) {
    float s = g_scale;
    float nf = (float)((1 << ((*wbits) - 1)) - 1);
    int t = blockIdx.x * blockDim.x + threadIdx.x;   // over FOUT*K_IN/4
    float4 w = ((const float4*)W)[t];
    float m0 = fminf(fmaxf(rintf(__fdiv_rn(w.x, s)), -nf), nf);
    float m1 = fminf(fmaxf(rintf(__fdiv_rn(w.y, s)), -nf), nf);
    float m2 = fminf(fmaxf(rintf(__fdiv_rn(w.z, s)), -nf), nf);
    float m3 = fminf(fmaxf(rintf(__fdiv_rn(w.w, s)), -nf), nf);
    char4 c = make_char4((char)(int)m0, (char)(int)m1, (char)(int)m2, (char)(int)m3);
    *(char4*)&g_Bq[(size_t)t * 4] = c;
}

// Fused: per-row max + 3-digit int8 encoding (row stays in registers)
__global__ void rowdig_kernel(const float* __restrict__ x) {
    __shared__ float red[8];
    __shared__ float bc[2];
    const int row = blockIdx.x;
    const int tid = threadIdx.x;
    const float4* p = (const float4*)(x + (size_t)row * K_IN);
    float4 v[4];
    float m = 0.f;
    #pragma unroll
    for (int i = 0; i < 4; i++) {
        v[i] = p[tid + i * 256];
        m = fmaxf(m, fmaxf(fmaxf(fabsf(v[i].x), fabsf(v[i].y)),
                           fmaxf(fabsf(v[i].z), fabsf(v[i].w))));
    }
    #pragma unroll
    for (int o = 16; o > 0; o >>= 1)
        m = fmaxf(m, __shfl_xor_sync(0xffffffffu, m, o));
    if ((tid & 31) == 0) red[tid >> 5] = m;
    __syncthreads();
    if (tid == 0) {
        float mm = red[0];
        #pragma unroll
        for (int i = 1; i < 8; i++) mm = fmaxf(mm, red[i]);
        float sn = __fdiv_rn(mm, 127.f);
        float inv = __fdiv_rn(127.f, mm);
        g_sn[row] = sn;
        bc[0] = sn; bc[1] = inv;
    }
    __syncthreads();
    const float sn = bc[0];
    const float inv = bc[1];
    const float s2 = sn * INV254;
    const float inv2 = inv * 254.f;
    const float inv3 = inv2 * 254.f;
    #pragma unroll
    for (int i = 0; i < 4; i++) {
        const int col = (tid + i * 256) * 4;
        float e[4] = {v[i].x, v[i].y, v[i].z, v[i].w};
        float X1[4], X2[4], X3[4];
        #pragma unroll
        for (int j = 0; j < 4; j++) {
            float d1 = fminf(fmaxf(rintf(e[j] * inv), -127.f), 127.f);
            float r1 = fmaf(-d1, sn, e[j]);
            float d2 = fminf(fmaxf(rintf(r1 * inv2), -127.f), 127.f);
            float r2 = fmaf(-d2, s2, r1);
            float d3 = fminf(fmaxf(rintf(r2 * inv3), -127.f), 127.f);
            X1[j] = d1; X2[j] = d2; X3[j] = d3;
        }
        char4 c1 = make_char4((char)(int)X1[0], (char)(int)X1[1],
                              (char)(int)X1[2], (char)(int)X1[3]);
        char4 c2 = make_char4((char)(int)X2[0], (char)(int)X2[1],
                              (char)(int)X2[2], (char)(int)X2[3]);
        char4 c3 = make_char4((char)(int)X3[0], (char)(int)X3[1],
                              (char)(int)X3[2], (char)(int)X3[3]);
        *(char4*)&g_Ad[(size_t)row * (3 * K_IN) + col] = c1;
        *(char4*)&g_Ad[(size_t)row * (3 * K_IN) + K_IN + col] = c2;
        *(char4*)&g_Ad[(size_t)row * (3 * K_IN) + 2 * K_IN + col] = c3;
    }
}

// ------- Merged GEMM: all 3 digits, one pass.  g_G = s*(sn*G1+s2*G2+s3*G3) -------
// Static smem: 2 stages x [X1|X2|X3|B] x 128 rows x 32B (32 KB) + stats red.
__global__ void __launch_bounds__(256) gemm_imma3() {
    __shared__ char sbuf[2][4][MAT32B];
    __shared__ float red[8][4][16];      // cross-warp stats reduction (2 KB)

    const int tid = threadIdx.x;
    const int wid = tid >> 5;
    const int lane = tid & 31;
    const int wm = wid & 1;
    const int wn = wid >> 1;

    const int cid = blockIdx.x;
    const int sup = cid >> 8;
    const int rem = cid & 255;
    const int tm = ((sup & 3) << 4) | (rem & 15);
    const int tn = ((sup >> 2) << 4) | (rem >> 4);

    int acc1[4][4][4], acc2[4][4][4], acc3[4][4][4];
    #pragma unroll
    for (int a = 0; a < 4; a++)
        #pragma unroll
        for (int b = 0; b < 4; b++)
            #pragma unroll
            for (int c = 0; c < 4; c++) {
                acc1[a][b][c] = 0; acc2[a][b][c] = 0; acc3[a][b][c] = 0;
            }

    // loaders: 1024 16B-chunks per stage (4 mats x 128 rows x 2), 4 per thread
    const char* gsrc[4];
    uint32_t doff[4];
    #pragma unroll
    for (int j = 0; j < 4; j++) {
        int id = j * 256 + tid;
        int mat = id >> 8;           // 0=X1, 1=X2, 2=X3, 3=B
        int r2 = id & 255;
        int row = r2 >> 1;
        int c16 = r2 & 1;
        if (mat < 3)
            gsrc[j] = (const char*)g_Ad + (size_t)(tm * BM + row) * (3 * K_IN)
                      + mat * K_IN + c16 * 16;
        else
            gsrc[j] = (const char*)g_Bq + (size_t)(tn * BN + row) * K_IN + c16 * 16;
        doff[j] = (uint32_t)(mat * MAT32B + row * 32 + SWZ32(row, c16));
    }
    const uint32_t base_u[2] = { smem_u32(sbuf[0]), smem_u32(sbuf[1]) };

    #pragma unroll
    for (int j = 0; j < 4; j++) CP_ASYNC16(base_u[0] + doff[j], gsrc[j]);
    CP_COMMIT();

    for (int i = 0; i < NCH; i++) {
        const int b = i & 1;
        if (i + 1 < NCH) {
            const int nb = (i + 1) & 1;
            const size_t ko = (size_t)(i + 1) * BKB;
            #pragma unroll
            for (int j = 0; j < 4; j++)
                CP_ASYNC16(base_u[nb] + doff[j], gsrc[j] + ko);
            CP_COMMIT();
            CP_WAIT1();
        } else {
            CP_WAIT0();
        }
        __syncthreads();

        const uint32_t sX1 = base_u[b];
        const uint32_t sX2 = base_u[b] + MAT32B;
        const uint32_t sX3 = base_u[b] + 2 * MAT32B;
        const uint32_t sB  = base_u[b] + 3 * MAT32B;

        // B: 2 ldmatrix.x4 cover 4 n-tiles (k32)
        uint32_t bf[4][2];
        #pragma unroll
        for (int g = 0; g < 2; g++) {
            const int brow = wn * 32 + g * 16 + ((lane >> 4) << 3) + (lane & 7);
            const int bc16 = (lane >> 3) & 1;
            uint32_t r[4];
            ldm_x4(r, sB + (uint32_t)(brow * 32 + SWZ32(brow, bc16)));
            bf[2 * g][0] = r[0]; bf[2 * g][1] = r[1];
            bf[2 * g + 1][0] = r[2]; bf[2 * g + 1][1] = r[3];
        }
        #pragma unroll
        for (int mt = 0; mt < 4; mt++) {
            const int arow = wm * 64 + mt * 16 + (lane & 15);
            const int ac16 = lane >> 4;
            const uint32_t aoff = (uint32_t)(arow * 32 + SWZ32(arow, ac16));
            uint32_t a1[4], a2[4], a3[4];
            ldm_x4(a1, sX1 + aoff);
            ldm_x4(a2, sX2 + aoff);
            ldm_x4(a3, sX3 + aoff);
            #pragma unroll
            for (int nt = 0; nt < 4; nt++) {
                imma(acc1[mt][nt], a1, bf[nt][0], bf[nt][1]);
                imma(acc2[mt][nt], a2, bf[nt][0], bf[nt][1]);
                imma(acc3[mt][nt], a3, bf[nt][0], bf[nt][1]);
            }
        }
        __syncthreads();
    }

    // epilogue: g_G = f1*G1 + f2*G2 + f3*G3 (single write), fused stats partials
    const float s = g_scale;
    const int rbase = tm * BM + wm * 64 + (lane >> 2);
    const int cbase = tn * BN + wn * 32 + 2 * (lane & 3);
    float cs[4][2], cq[4][2];
    #pragma unroll
    for (int nt = 0; nt < 4; nt++) {
        cs[nt][0] = 0.f; cs[nt][1] = 0.f;
        cq[nt][0] = 0.f; cq[nt][1] = 0.f;
    }
    #pragma unroll
    for (int mt = 0; mt < 4; mt++) {
        const int r0 = rbase + mt * 16;
        const int r1 = r0 + 8;
        const float f10 = s * g_sn[r0];
        const float f20 = f10 * INV254;
        const float f30 = f20 * INV254;
        const float f11 = s * g_sn[r1];
        const float f21 = f11 * INV254;
        const float f31 = f21 * INV254;
        #pragma unroll
        for (int nt = 0; nt < 4; nt++) {
            const int cc = cbase + nt * 8;
            float2 v0, v1;
            v0.x = fmaf(f10, (float)acc1[mt][nt][0],
                        fmaf(f20, (float)acc2[mt][nt][0], f30 * (float)acc3[mt][nt][0]));
            v0.y = fmaf(f10, (float)acc1[mt][nt][1],
                        fmaf(f20, (float)acc2[mt][nt][1], f30 * (float)acc3[mt][nt][1]));
            v1.x = fmaf(f11, (float)acc1[mt][nt][2],
                        fmaf(f21, (float)acc2[mt][nt][2], f31 * (float)acc3[mt][nt][2]));
            v1.y = fmaf(f11, (float)acc1[mt][nt][3],
                        fmaf(f21, (float)acc2[mt][nt][3], f31 * (float)acc3[mt][nt][3]));
            *(float2*)&g_G[(size_t)r0 * FOUT + cc] = v0;
            *(float2*)&g_G[(size_t)r1 * FOUT + cc] = v1;
            cs[nt][0] += v0.x + v1.x;   cs[nt][1] += v0.y + v1.y;
            cq[nt][0] = fmaf(v0.x, v0.x, fmaf(v1.x, v1.x, cq[nt][0]));
            cq[nt][1] = fmaf(v0.y, v0.y, fmaf(v1.y, v1.y, cq[nt][1]));
        }
    }
    // reduce over the 8 threads (stride 4) sharing the same columns
    #pragma unroll
    for (int o = 16; o >= 4; o >>= 1) {
        #pragma unroll
        for (int nt = 0; nt < 4; nt++) {
            cs[nt][0] += __shfl_down_sync(0xffffffffu, cs[nt][0], o);
            cs[nt][1] += __shfl_down_sync(0xffffffffu, cs[nt][1], o);
            cq[nt][0] += __shfl_down_sync(0xffffffffu, cq[nt][0], o);
            cq[nt][1] += __shfl_down_sync(0xffffffffu, cq[nt][1], o);
        }
    }
    if (lane < 4) {
        #pragma unroll
        for (int nt = 0; nt < 4; nt++) {
            red[wid][lane][nt * 2]     = cs[nt][0];
            red[wid][lane][nt * 2 + 1] = cs[nt][1];
            red[wid][lane][8 + nt * 2]     = cq[nt][0];
            red[wid][lane][8 + nt * 2 + 1] = cq[nt][1];
        }
    }
    __syncthreads();
    if (wm == 0 && lane < 4) {
        const int col0 = tn * BN + wn * 32 + 2 * lane;
        #pragma unroll
        for (int nt = 0; nt < 4; nt++) {
            #pragma unroll
            for (int h = 0; h < 2; h++) {
                float ssum = red[wid][lane][nt * 2 + h] + red[wid + 1][lane][nt * 2 + h];
                float qsum = red[wid][lane][8 + nt * 2 + h] + red[wid + 1][lane][8 + nt * 2 + h];
                g_psum2[tm][col0 + nt * 8 + h] = ssum;
                g_psq2[tm][col0 + nt * 8 + h] = qsum;
            }
        }
    }
}

// ---------------- coef + BN + act-quant ----------------
__global__ void coef_kernel(int Nr, int Nc) {
    int c = blockIdx.x * blockDim.x + threadIdx.x;
    if (c >= Nc) return;
    float s = 0.f, q = 0.f;
    #pragma unroll 8
    for (int i = 0; i < MT; i++) { s += g_psum2[i][c]; q += g_psq2[i][c]; }
    float mean = s / (float)Nr;
    float ex2  = q / (float)Nr;
    float var  = ex2 - mean * mean;
    g_mean[c] = mean;
    g_rstd[c] = (float)(1.0 / sqrt((double)var + 1e-5));
}

__global__ void bnq_kernel(const float* __restrict__ gamma,
                           const float* __restrict__ beta,
                           const int* __restrict__ abits,
                           float* __restrict__ out, int total, int Nc) {
    float na = (float)((1 << (*abits)) - 1);
    for (int i = blockIdx.x * blockDim.x + threadIdx.x; i < total;
         i += gridDim.x * blockDim.x) {
        int c = i % Nc;
        float g = g_G[i];
        float y = gamma[c] * (g - g_mean[c]) * g_rstd[c] + beta[c];
        float yc = fminf(fmaxf(y, 0.f), 1.f);
        float q = __fdiv_rn(rintf(yc * na), na);
        out[i] = yc + (q - yc);
    }
}

// ---------------- launch ----------------
extern "C" void kernel_launch(void* const* d_in, const int* in_sizes, int n_in,
                              void* d_out, int out_size) {
    const float* x     = (const float*)d_in[0];
    const float* W     = (const float*)d_in[1];
    const float* gamma = (const float*)d_in[2];
    const float* beta  = (const float*)d_in[3];
    const int*   wbits = (const int*)d_in[4];
    const int*   abits = (const int*)d_in[5];

    init_kernel<<<1, 32>>>();
    maxabs_kernel<<<256, 256>>>(W, FOUT * K_IN);
    scale_kernel<<<1, 1>>>(wbits);
    quantm_kernel<<<(FOUT * K_IN / 4) / 256, 256>>>(W, wbits);
    rowdig_kernel<<<NROW, 256>>>(x);

    gemm_imma3<<<MT * NT, 256>>>();

    coef_kernel<<<(FOUT + 255) / 256, 256>>>(NROW, FOUT);
    bnq_kernel<<<2048, 256>>>(gamma, beta, abits, (float*)d_out,
                              NROW * FOUT, FOUT);
}

// round 14
// speedup vs baseline: 1.0143x; 1.0143x over previous
#include <cuda_runtime.h>
#include <math.h>
#include <stdint.h>

// Fixed problem shape (verified R1: x[8192,4096], W[4096,4096])
#define K_IN 4096
#define NROW 8192
#define FOUT 4096

#define BM 128
#define BN 128
#define BKB 64                // K bytes per stage (64 int8)
#define NCH (K_IN / BKB)      // 64
#define MT (NROW / BM)        // 64
#define NT (FOUT / BN)        // 32
#define MATB (BM * 64)        // 8192 B per matrix per stage
#define INV254 (1.f / 254.f)

// XOR swizzle: 16B-chunk index within a 64B row, keyed by row
#define SWZ(row, c16) (((c16) ^ (((row) >> 1) & 3)) << 4)

// ---------------- device scratch ----------------
__device__ int8_t g_Ad[(size_t)NROW * (3 * K_IN)];  // [X1 | X2 | X3] per row
__device__ int8_t g_Bq[(size_t)FOUT * K_IN];        // weight codes m
__device__ float g_G[(size_t)NROW * FOUT];
__device__ float g_sn[NROW];                        // per-row scale s_n
__device__ unsigned int g_maxbits;
__device__ float g_scale;
__device__ float g_psum2[MT][FOUT];                 // per-row-block partial sums
__device__ float g_psq2[MT][FOUT];
__device__ float g_mean[FOUT];
__device__ float g_rstd[FOUT];

// ---------------- helpers (sm_80-era PTX: legal at compute_100) ----------------
__device__ __forceinline__ uint32_t smem_u32(const void* p) {
    return (uint32_t)__cvta_generic_to_shared(p);
}
#define CP_ASYNC16(dst, src) \
    asm volatile("cp.async.cg.shared.global [%0], [%1], 16;" :: "r"(dst), "l"(src) : "memory")
#define CP_COMMIT() asm volatile("cp.async.commit_group;" ::: "memory")
#define CP_WAIT1()  asm volatile("cp.async.wait_group 1;" ::: "memory")
#define CP_WAIT0()  asm volatile("cp.async.wait_group 0;" ::: "memory")

__device__ __forceinline__ void ldm_x4(uint32_t* r, uint32_t addr) {
    asm volatile("ldmatrix.sync.aligned.m8n8.x4.shared.b16 {%0,%1,%2,%3}, [%4];"
                 : "=r"(r[0]), "=r"(r[1]), "=r"(r[2]), "=r"(r[3]) : "r"(addr));
}
__device__ __forceinline__ void imma(int* d, const uint32_t* a, uint32_t b0, uint32_t b1) {
    asm volatile(
        "mma.sync.aligned.m16n8k32.row.col.s32.s8.s8.s32 "
        "{%0,%1,%2,%3}, {%4,%5,%6,%7}, {%8,%9}, {%0,%1,%2,%3};"
        : "+r"(d[0]), "+r"(d[1]), "+r"(d[2]), "+r"(d[3])
        : "r"(a[0]), "r"(a[1]), "r"(a[2]), "r"(a[3]), "r"(b0), "r"(b1));
}

// ---------------- small kernels ----------------
__global__ void init_kernel() { if (threadIdx.x == 0) g_maxbits = 0u; }

__global__ void maxabs_kernel(const float* __restrict__ W, int n) {
    float m = 0.f;
    for (int i = blockIdx.x * blockDim.x + threadIdx.x; i < n;
         i += gridDim.x * blockDim.x)
        m = fmaxf(m, fabsf(W[i]));
    #pragma unroll
    for (int o = 16; o > 0; o >>= 1)
        m = fmaxf(m, __shfl_xor_sync(0xffffffffu, m, o));
    if ((threadIdx.x & 31) == 0)
        atomicMax(&g_maxbits, __float_as_uint(m));
}

__global__ void scale_kernel(const int* __restrict__ wbits) {
    float nf = (float)((1 << ((*wbits) - 1)) - 1);
    g_scale = __fdiv_rn(__uint_as_float(g_maxbits), nf);
}

// W -> integer codes m (int8)
__global__ void quantm_kernel(const float* __restrict__ W,
                              const int* __restrict__ wbits) {
    float s = g_scale;
    float nf = (float)((1 << ((*wbits) - 1)) - 1);
    int t = blockIdx.x * blockDim.x + threadIdx.x;   // over FOUT*K_IN/4
    float4 w = ((const float4*)W)[t];
    float m0 = fminf(fmaxf(rintf(__fdiv_rn(w.x, s)), -nf), nf);
    float m1 = fminf(fmaxf(rintf(__fdiv_rn(w.y, s)), -nf), nf);
    float m2 = fminf(fmaxf(rintf(__fdiv_rn(w.z, s)), -nf), nf);
    float m3 = fminf(fmaxf(rintf(__fdiv_rn(w.w, s)), -nf), nf);
    char4 c = make_char4((char)(int)m0, (char)(int)m1, (char)(int)m2, (char)(int)m3);
    *(char4*)&g_Bq[(size_t)t * 4] = c;
}

// Fused: per-row max + 3-digit int8 encoding (row stays in registers)
__global__ void rowdig_kernel(const float* __restrict__ x) {
    __shared__ float red[8];
    __shared__ float bc[2];
    const int row = blockIdx.x;
    const int tid = threadIdx.x;
    const float4* p = (const float4*)(x + (size_t)row * K_IN);
    float4 v[4];
    float m = 0.f;
    #pragma unroll
    for (int i = 0; i < 4; i++) {
        v[i] = p[tid + i * 256];
        m = fmaxf(m, fmaxf(fmaxf(fabsf(v[i].x), fabsf(v[i].y)),
                           fmaxf(fabsf(v[i].z), fabsf(v[i].w))));
    }
    #pragma unroll
    for (int o = 16; o > 0; o >>= 1)
        m = fmaxf(m, __shfl_xor_sync(0xffffffffu, m, o));
    if ((tid & 31) == 0) red[tid >> 5] = m;
    __syncthreads();
    if (tid == 0) {
        float mm = red[0];
        #pragma unroll
        for (int i = 1; i < 8; i++) mm = fmaxf(mm, red[i]);
        float sn = __fdiv_rn(mm, 127.f);
        float inv = __fdiv_rn(127.f, mm);
        g_sn[row] = sn;
        bc[0] = sn; bc[1] = inv;
    }
    __syncthreads();
    const float sn = bc[0];
    const float inv = bc[1];
    const float s2 = sn * INV254;
    const float inv2 = inv * 254.f;
    const float inv3 = inv2 * 254.f;
    #pragma unroll
    for (int i = 0; i < 4; i++) {
        const int col = (tid + i * 256) * 4;
        float e[4] = {v[i].x, v[i].y, v[i].z, v[i].w};
        float X1[4], X2[4], X3[4];
        #pragma unroll
        for (int j = 0; j < 4; j++) {
            float d1 = fminf(fmaxf(rintf(e[j] * inv), -127.f), 127.f);
            float r1 = fmaf(-d1, sn, e[j]);
            float d2 = fminf(fmaxf(rintf(r1 * inv2), -127.f), 127.f);
            float r2 = fmaf(-d2, s2, r1);
            float d3 = fminf(fmaxf(rintf(r2 * inv3), -127.f), 127.f);
            X1[j] = d1; X2[j] = d2; X3[j] = d3;
        }
        char4 c1 = make_char4((char)(int)X1[0], (char)(int)X1[1],
                              (char)(int)X1[2], (char)(int)X1[3]);
        char4 c2 = make_char4((char)(int)X2[0], (char)(int)X2[1],
                              (char)(int)X2[2], (char)(int)X2[3]);
        char4 c3 = make_char4((char)(int)X3[0], (char)(int)X3[1],
                              (char)(int)X3[2], (char)(int)X3[3]);
        *(char4*)&g_Ad[(size_t)row * (3 * K_IN) + col] = c1;
        *(char4*)&g_Ad[(size_t)row * (3 * K_IN) + K_IN + col] = c2;
        *(char4*)&g_Ad[(size_t)row * (3 * K_IN) + 2 * K_IN + col] = c3;
    }
}

// ------- Fused GEMM: two sequential K-passes (digits 1+2, then digit 3) -------
// Phase 1 mirrors R11's k1 (48 KB smem, 128 int accs), folds to 64 fp32 regs.
// Phase 2 mirrors R11's k2 mainloop reusing smem + acc array, then single G
// write + fused BN stats partials. Stats reduction scratch ALIASES the tile
// buffer (last tile read precedes a __syncthreads before the aliased writes).
__global__ void __launch_bounds__(256) gemm_fused() {
    __shared__ char sbuf[2][3][MATB];    // 48 KB exactly (0xc000)

    const int tid = threadIdx.x;
    const int wid = tid >> 5;
    const int lane = tid & 31;
    const int wm = wid & 1;
    const int wn = wid >> 1;

    const int cid = blockIdx.x;
    const int sup = cid >> 8;
    const int rem = cid & 255;
    const int tm = ((sup & 3) << 4) | (rem & 15);
    const int tn = ((sup >> 2) << 4) | (rem >> 4);

    const uint32_t base_u[2] = { smem_u32(sbuf[0]), smem_u32(sbuf[1]) };
    const float s = g_scale;
    const int rbase = tm * BM + wm * 64 + (lane >> 2);
    const int cbase = tn * BN + wn * 32 + 2 * (lane & 3);

    float facc[4][4][4];

    // ================= Phase 1: digits 1 + 2 =================
    {
        int acc1[4][4][4], acc2[4][4][4];
        #pragma unroll
        for (int a = 0; a < 4; a++)
            #pragma unroll
            for (int b = 0; b < 4; b++)
                #pragma unroll
                for (int c = 0; c < 4; c++) { acc1[a][b][c] = 0; acc2[a][b][c] = 0; }

        const char* gsrc[6];
        uint32_t doff[6];
        #pragma unroll
        for (int j = 0; j < 6; j++) {
            int id = j * 256 + tid;
            int mat = id >> 9;           // 0=X1, 1=X2, 2=B
            int r2 = id & 511;
            int row = r2 >> 2;
            int c16 = r2 & 3;
            if (mat == 0)
                gsrc[j] = (const char*)g_Ad + (size_t)(tm * BM + row) * (3 * K_IN) + c16 * 16;
            else if (mat == 1)
                gsrc[j] = (const char*)g_Ad + (size_t)(tm * BM + row) * (3 * K_IN) + K_IN + c16 * 16;
            else
                gsrc[j] = (const char*)g_Bq + (size_t)(tn * BN + row) * K_IN + c16 * 16;
            doff[j] = (uint32_t)(mat * MATB + row * 64 + SWZ(row, c16));
        }

        #pragma unroll
        for (int j = 0; j < 6; j++) CP_ASYNC16(base_u[0] + doff[j], gsrc[j]);
        CP_COMMIT();

        for (int i = 0; i < NCH; i++) {
            const int b = i & 1;
            if (i + 1 < NCH) {
                const int nb = (i + 1) & 1;
                const size_t ko = (size_t)(i + 1) * BKB;
                #pragma unroll
                for (int j = 0; j < 6; j++)
                    CP_ASYNC16(base_u[nb] + doff[j], gsrc[j] + ko);
                CP_COMMIT();
                CP_WAIT1();
            } else {
                CP_WAIT0();
            }
            __syncthreads();

            const uint32_t sA1 = base_u[b];
            const uint32_t sA2 = base_u[b] + MATB;
            const uint32_t sB  = base_u[b] + 2 * MATB;

            #pragma unroll
            for (int ks = 0; ks < 2; ks++) {
                uint32_t bf[4][2];
                #pragma unroll
                for (int g = 0; g < 2; g++) {
                    const int brow = wn * 32 + g * 16 + ((lane >> 4) << 3) + (lane & 7);
                    const int bc16 = ks * 2 + ((lane >> 3) & 1);
                    uint32_t r[4];
                    ldm_x4(r, sB + (uint32_t)(brow * 64 + SWZ(brow, bc16)));
                    bf[2 * g][0] = r[0]; bf[2 * g][1] = r[1];
                    bf[2 * g + 1][0] = r[2]; bf[2 * g + 1][1] = r[3];
                }
                #pragma unroll
                for (int mt = 0; mt < 4; mt++) {
                    const int arow = wm * 64 + mt * 16 + (lane & 15);
                    const int ac16 = ks * 2 + (lane >> 4);
                    const uint32_t aoff = (uint32_t)(arow * 64 + SWZ(arow, ac16));
                    uint32_t a1[4], a2[4];
                    ldm_x4(a1, sA1 + aoff);
                    ldm_x4(a2, sA2 + aoff);
                    #pragma unroll
                    for (int nt = 0; nt < 4; nt++) {
                        imma(acc1[mt][nt], a1, bf[nt][0], bf[nt][1]);
                        imma(acc2[mt][nt], a2, bf[nt][0], bf[nt][1]);
                    }
                }
            }
            __syncthreads();
        }

        // fold digits 1+2 into fp32 (same expression as R11 k1 epilogue)
        #pragma unroll
        for (int mt = 0; mt < 4; mt++) {
            const int r0 = rbase + mt * 16;
            const int r1 = r0 + 8;
            const float f10 = s * g_sn[r0];
            const float f20 = f10 * INV254;
            const float f11 = s * g_sn[r1];
            const float f21 = f11 * INV254;
            #pragma unroll
            for (int nt = 0; nt < 4; nt++) {
                facc[mt][nt][0] = fmaf(f10, (float)acc1[mt][nt][0], f20 * (float)acc2[mt][nt][0]);
                facc[mt][nt][1] = fmaf(f10, (float)acc1[mt][nt][1], f20 * (float)acc2[mt][nt][1]);
                facc[mt][nt][2] = fmaf(f11, (float)acc1[mt][nt][2], f21 * (float)acc2[mt][nt][2]);
                facc[mt][nt][3] = fmaf(f11, (float)acc1[mt][nt][3], f21 * (float)acc2[mt][nt][3]);
            }
        }
    }

    // ================= Phase 2: digit 3 =================
    {
        int acc3[4][4][4];
        #pragma unroll
        for (int a = 0; a < 4; a++)
            #pragma unroll
            for (int b = 0; b < 4; b++)
                #pragma unroll
                for (int c = 0; c < 4; c++) acc3[a][b][c] = 0;

        const char* gsrc[4];
        uint32_t doff[4];
        #pragma unroll
        for (int j = 0; j < 4; j++) {
            int id = j * 256 + tid;
            int mat = id >> 9;           // 0=X3, 1=B
            int r2 = id & 511;
            int row = r2 >> 2;
            int c16 = r2 & 3;
            if (mat == 0)
                gsrc[j] = (const char*)g_Ad + (size_t)(tm * BM + row) * (3 * K_IN)
                          + 2 * K_IN + c16 * 16;
            else
                gsrc[j] = (const char*)g_Bq + (size_t)(tn * BN + row) * K_IN + c16 * 16;
            doff[j] = (uint32_t)(mat * MATB + row * 64 + SWZ(row, c16));
        }

        // Phase-1 mainloop ended with __syncthreads(); safe to refill stage 0.
        #pragma unroll
        for (int j = 0; j < 4; j++) CP_ASYNC16(base_u[0] + doff[j], gsrc[j]);
        CP_COMMIT();

        for (int i = 0; i < NCH; i++) {
            const int b = i & 1;
            if (i + 1 < NCH) {
                const int nb = (i + 1) & 1;
                const size_t ko = (size_t)(i + 1) * BKB;
                #pragma unroll
                for (int j = 0; j < 4; j++)
                    CP_ASYNC16(base_u[nb] + doff[j], gsrc[j] + ko);
                CP_COMMIT();
                CP_WAIT1();
            } else {
                CP_WAIT0();
            }
            __syncthreads();

            const uint32_t sA3 = base_u[b];
            const uint32_t sB  = base_u[b] + MATB;

            #pragma unroll
            for (int ks = 0; ks < 2; ks++) {
                uint32_t bf[4][2];
                #pragma unroll
                for (int g = 0; g < 2; g++) {
                    const int brow = wn * 32 + g * 16 + ((lane >> 4) << 3) + (lane & 7);
                    const int bc16 = ks * 2 + ((lane >> 3) & 1);
                    uint32_t r[4];
                    ldm_x4(r, sB + (uint32_t)(brow * 64 + SWZ(brow, bc16)));
                    bf[2 * g][0] = r[0]; bf[2 * g][1] = r[1];
                    bf[2 * g + 1][0] = r[2]; bf[2 * g + 1][1] = r[3];
                }
                #pragma unroll
                for (int mt = 0; mt < 4; mt++) {
                    const int arow = wm * 64 + mt * 16 + (lane & 15);
                    const int ac16 = ks * 2 + (lane >> 4);
                    uint32_t a3[4];
                    ldm_x4(a3, sA3 + (uint32_t)(arow * 64 + SWZ(arow, ac16)));
                    #pragma unroll
                    for (int nt = 0; nt < 4; nt++)
                        imma(acc3[mt][nt], a3, bf[nt][0], bf[nt][1]);
                }
            }
            __syncthreads();
        }

        // final: facc += f3*G3, single G write, fused stats partials
        float cs[4][2], cq[4][2];
        #pragma unroll
        for (int nt = 0; nt < 4; nt++) {
            cs[nt][0] = 0.f; cs[nt][1] = 0.f;
            cq[nt][0] = 0.f; cq[nt][1] = 0.f;
        }
        #pragma unroll
        for (int mt = 0; mt < 4; mt++) {
            const int r0 = rbase + mt * 16;
            const int r1 = r0 + 8;
            const float f30 = ((s * g_sn[r0]) * INV254) * INV254;
            const float f31 = ((s * g_sn[r1]) * INV254) * INV254;
            #pragma unroll
            for (int nt = 0; nt < 4; nt++) {
                const int cc = cbase + nt * 8;
                float2 v0, v1;
                v0.x = fmaf(f30, (float)acc3[mt][nt][0], facc[mt][nt][0]);
                v0.y = fmaf(f30, (float)acc3[mt][nt][1], facc[mt][nt][1]);
                v1.x = fmaf(f31, (float)acc3[mt][nt][2], facc[mt][nt][2]);
                v1.y = fmaf(f31, (float)acc3[mt][nt][3], facc[mt][nt][3]);
                *(float2*)&g_G[(size_t)r0 * FOUT + cc] = v0;
                *(float2*)&g_G[(size_t)r1 * FOUT + cc] = v1;
                cs[nt][0] += v0.x + v1.x;   cs[nt][1] += v0.y + v1.y;
                cq[nt][0] = fmaf(v0.x, v0.x, fmaf(v1.x, v1.x, cq[nt][0]));
                cq[nt][1] = fmaf(v0.y, v0.y, fmaf(v1.y, v1.y, cq[nt][1]));
            }
        }
        #pragma unroll
        for (int o = 16; o >= 4; o >>= 1) {
            #pragma unroll
            for (int nt = 0; nt < 4; nt++) {
                cs[nt][0] += __shfl_down_sync(0xffffffffu, cs[nt][0], o);
                cs[nt][1] += __shfl_down_sync(0xffffffffu, cs[nt][1], o);
                cq[nt][0] += __shfl_down_sync(0xffffffffu, cq[nt][0], o);
                cq[nt][1] += __shfl_down_sync(0xffffffffu, cq[nt][1], o);
            }
        }
        // stats reduction scratch aliases the tile buffer (tile reads are done;
        // the mainloop's trailing __syncthreads orders them before these writes)
        float (*red)[4][16] = (float (*)[4][16])sbuf;
        if (lane < 4) {
            #pragma unroll
            for (int nt = 0; nt < 4; nt++) {
                red[wid][lane][nt * 2]     = cs[nt][0];
                red[wid][lane][nt * 2 + 1] = cs[nt][1];
                red[wid][lane][8 + nt * 2]     = cq[nt][0];
                red[wid][lane][8 + nt * 2 + 1] = cq[nt][1];
            }
        }
        __syncthreads();
        if (wm == 0 && lane < 4) {
            const int col0 = tn * BN + wn * 32 + 2 * lane;
            #pragma unroll
            for (int nt = 0; nt < 4; nt++) {
                #pragma unroll
                for (int h = 0; h < 2; h++) {
                    float ssum = red[wid][lane][nt * 2 + h] + red[wid + 1][lane][nt * 2 + h];
                    float qsum = red[wid][lane][8 + nt * 2 + h] + red[wid + 1][lane][8 + nt * 2 + h];
                    g_psum2[tm][col0 + nt * 8 + h] = ssum;
                    g_psq2[tm][col0 + nt * 8 + h] = qsum;
                }
            }
        }
    }
}

// ---------------- coef + BN + act-quant ----------------
__global__ void coef_kernel(int Nr, int Nc) {
    int c = blockIdx.x * blockDim.x + threadIdx.x;
    if (c >= Nc) return;
    float s = 0.f, q = 0.f;
    #pragma unroll 8
    for (int i = 0; i < MT; i++) { s += g_psum2[i][c]; q += g_psq2[i][c]; }
    float mean = s / (float)Nr;
    float ex2  = q / (float)Nr;
    float var  = ex2 - mean * mean;
    g_mean[c] = mean;
    g_rstd[c] = (float)(1.0 / sqrt((double)var + 1e-5));
}

__global__ void bnq_kernel(const float* __restrict__ gamma,
                           const float* __restrict__ beta,
                           const int* __restrict__ abits,
                           float* __restrict__ out, int total, int Nc) {
    float na = (float)((1 << (*abits)) - 1);
    for (int i = blockIdx.x * blockDim.x + threadIdx.x; i < total;
         i += gridDim.x * blockDim.x) {
        int c = i % Nc;
        float g = g_G[i];
        float y = gamma[c] * (g - g_mean[c]) * g_rstd[c] + beta[c];
        float yc = fminf(fmaxf(y, 0.f), 1.f);
        float q = __fdiv_rn(rintf(yc * na), na);
        out[i] = yc + (q - yc);
    }
}

// ---------------- launch ----------------
extern "C" void kernel_launch(void* const* d_in, const int* in_sizes, int n_in,
                              void* d_out, int out_size) {
    const float* x     = (const float*)d_in[0];
    const float* W     = (const float*)d_in[1];
    const float* gamma = (const float*)d_in[2];
    const float* beta  = (const float*)d_in[3];
    const int*   wbits = (const int*)d_in[4];
    const int*   abits = (const int*)d_in[5];

    init_kernel<<<1, 32>>>();
    maxabs_kernel<<<256, 256>>>(W, FOUT * K_IN);
    scale_kernel<<<1, 1>>>(wbits);
    quantm_kernel<<<(FOUT * K_IN / 4) / 256, 256>>>(W, wbits);
    rowdig_kernel<<<NROW, 256>>>(x);

    gemm_fused<<<MT * NT, 256>>>();

    coef_kernel<<<(FOUT + 255) / 256, 256>>>(NROW, FOUT);
    bnq_kernel<<<2048, 256>>>(gamma, beta, abits, (float*)d_out,
                              NROW * FOUT, FOUT);
}

// round 15
// speedup vs baseline: 1.1347x; 1.1187x over previous
#include <cuda_runtime.h>
#include <math.h>
#include <stdint.h>

// Fixed problem shape (verified R1: x[8192,4096], W[4096,4096])
#define K_IN 4096
#define NROW 8192
#define FOUT 4096

#define BM 128
#define BN 128
#define BKB 64                // K bytes per stage (64 int8)
#define NCH (K_IN / BKB)      // 64
#define MT (NROW / BM)        // 64
#define NT (FOUT / BN)        // 32
#define MATB (BM * 64)        // 8192 B per matrix per stage
#define INV254 (1.f / 254.f)

// XOR swizzle: 16B-chunk index within a 64B row, keyed by row
#define SWZ(row, c16) (((c16) ^ (((row) >> 1) & 3)) << 4)

// ---------------- device scratch ----------------
__device__ int8_t g_Ad[(size_t)NROW * (3 * K_IN)];  // [X1 | X2 | X3] per row
__device__ int8_t g_Bq[(size_t)FOUT * K_IN];        // weight codes m
__device__ float g_G[(size_t)NROW * FOUT];
__device__ float g_sn[NROW];                        // per-row scale s_n
__device__ unsigned int g_maxbits;
__device__ float g_scale;
__device__ float g_psum2[MT][FOUT];                 // per-row-block partial sums
__device__ float g_psq2[MT][FOUT];
__device__ float g_mean[FOUT];
__device__ float g_rstd[FOUT];

// ---------------- helpers (sm_80-era PTX: legal at compute_100) ----------------
__device__ __forceinline__ uint32_t smem_u32(const void* p) {
    return (uint32_t)__cvta_generic_to_shared(p);
}
#define CP_ASYNC16(dst, src) \
    asm volatile("cp.async.cg.shared.global [%0], [%1], 16;" :: "r"(dst), "l"(src) : "memory")
#define CP_COMMIT() asm volatile("cp.async.commit_group;" ::: "memory")
#define CP_WAIT1()  asm volatile("cp.async.wait_group 1;" ::: "memory")
#define CP_WAIT0()  asm volatile("cp.async.wait_group 0;" ::: "memory")

__device__ __forceinline__ void ldm_x4(uint32_t* r, uint32_t addr) {
    asm volatile("ldmatrix.sync.aligned.m8n8.x4.shared.b16 {%0,%1,%2,%3}, [%4];"
                 : "=r"(r[0]), "=r"(r[1]), "=r"(r[2]), "=r"(r[3]) : "r"(addr));
}
__device__ __forceinline__ void imma(int* d, const uint32_t* a, uint32_t b0, uint32_t b1) {
    asm volatile(
        "mma.sync.aligned.m16n8k32.row.col.s32.s8.s8.s32 "
        "{%0,%1,%2,%3}, {%4,%5,%6,%7}, {%8,%9}, {%0,%1,%2,%3};"
        : "+r"(d[0]), "+r"(d[1]), "+r"(d[2]), "+r"(d[3])
        : "r"(a[0]), "r"(a[1]), "r"(a[2]), "r"(a[3]), "r"(b0), "r"(b1));
}

// ---------------- small kernels ----------------
__global__ void init_kernel() { if (threadIdx.x == 0) g_maxbits = 0u; }

__global__ void maxabs_kernel(const float* __restrict__ W, int n) {
    float m = 0.f;
    for (int i = blockIdx.x * blockDim.x + threadIdx.x; i < n;
         i += gridDim.x * blockDim.x)
        m = fmaxf(m, fabsf(W[i]));
    #pragma unroll
    for (int o = 16; o > 0; o >>= 1)
        m = fmaxf(m, __shfl_xor_sync(0xffffffffu, m, o));
    if ((threadIdx.x & 31) == 0)
        atomicMax(&g_maxbits, __float_as_uint(m));
}

__global__ void scale_kernel(const int* __restrict__ wbits) {
    float nf = (float)((1 << ((*wbits) - 1)) - 1);
    g_scale = __fdiv_rn(__uint_as_float(g_maxbits), nf);
}

// W -> integer codes m (int8)
__global__ void quantm_kernel(const float* __restrict__ W,
                              const int* __restrict__ wbits) {
    float s = g_scale;
    float nf = (float)((1 << ((*wbits) - 1)) - 1);
    int t = blockIdx.x * blockDim.x + threadIdx.x;   // over FOUT*K_IN/4
    float4 w = ((const float4*)W)[t];
    float m0 = fminf(fmaxf(rintf(__fdiv_rn(w.x, s)), -nf), nf);
    float m1 = fminf(fmaxf(rintf(__fdiv_rn(w.y, s)), -nf), nf);
    float m2 = fminf(fmaxf(rintf(__fdiv_rn(w.z, s)), -nf), nf);
    float m3 = fminf(fmaxf(rintf(__fdiv_rn(w.w, s)), -nf), nf);
    char4 c = make_char4((char)(int)m0, (char)(int)m1, (char)(int)m2, (char)(int)m3);
    *(char4*)&g_Bq[(size_t)t * 4] = c;
}

// Fused: per-row max + 3-digit int8 encoding (row stays in registers)
__global__ void rowdig_kernel(const float* __restrict__ x) {
    __shared__ float red[8];
    __shared__ float bc[2];
    const int row = blockIdx.x;
    const int tid = threadIdx.x;
    const float4* p = (const float4*)(x + (size_t)row * K_IN);
    float4 v[4];
    float m = 0.f;
    #pragma unroll
    for (int i = 0; i < 4; i++) {
        v[i] = p[tid + i * 256];
        m = fmaxf(m, fmaxf(fmaxf(fabsf(v[i].x), fabsf(v[i].y)),
                           fmaxf(fabsf(v[i].z), fabsf(v[i].w))));
    }
    #pragma unroll
    for (int o = 16; o > 0; o >>= 1)
        m = fmaxf(m, __shfl_xor_sync(0xffffffffu, m, o));
    if ((tid & 31) == 0) red[tid >> 5] = m;
    __syncthreads();
    if (tid == 0) {
        float mm = red[0];
        #pragma unroll
        for (int i = 1; i < 8; i++) mm = fmaxf(mm, red[i]);
        float sn = __fdiv_rn(mm, 127.f);
        float inv = __fdiv_rn(127.f, mm);
        g_sn[row] = sn;
        bc[0] = sn; bc[1] = inv;
    }
    __syncthreads();
    const float sn = bc[0];
    const float inv = bc[1];
    const float s2 = sn * INV254;
    const float inv2 = inv * 254.f;
    const float inv3 = inv2 * 254.f;
    #pragma unroll
    for (int i = 0; i < 4; i++) {
        const int col = (tid + i * 256) * 4;
        float e[4] = {v[i].x, v[i].y, v[i].z, v[i].w};
        float X1[4], X2[4], X3[4];
        #pragma unroll
        for (int j = 0; j < 4; j++) {
            float d1 = fminf(fmaxf(rintf(e[j] * inv), -127.f), 127.f);
            float r1 = fmaf(-d1, sn, e[j]);
            float d2 = fminf(fmaxf(rintf(r1 * inv2), -127.f), 127.f);
            float r2 = fmaf(-d2, s2, r1);
            float d3 = fminf(fmaxf(rintf(r2 * inv3), -127.f), 127.f);
            X1[j] = d1; X2[j] = d2; X3[j] = d3;
        }
        char4 c1 = make_char4((char)(int)X1[0], (char)(int)X1[1],
                              (char)(int)X1[2], (char)(int)X1[3]);
        char4 c2 = make_char4((char)(int)X2[0], (char)(int)X2[1],
                              (char)(int)X2[2], (char)(int)X2[3]);
        char4 c3 = make_char4((char)(int)X3[0], (char)(int)X3[1],
                              (char)(int)X3[2], (char)(int)X3[3]);
        *(char4*)&g_Ad[(size_t)row * (3 * K_IN) + col] = c1;
        *(char4*)&g_Ad[(size_t)row * (3 * K_IN) + K_IN + col] = c2;
        *(char4*)&g_Ad[(size_t)row * (3 * K_IN) + 2 * K_IN + col] = c3;
    }
}

// ------- GEMM kernel 1: digits 1+2.  g_G = s*(sn*G1 + s2*G2) -------
__global__ void __launch_bounds__(256) gemm_imma2() {
    __shared__ char sbuf[2][3][MATB];    // [stage][X1|X2|B] = 48 KB

    const int tid = threadIdx.x;
    const int wid = tid >> 5;
    const int lane = tid & 31;
    const int wm = wid & 1;
    const int wn = wid >> 1;

    const int cid = blockIdx.x;
    const int sup = cid >> 8;
    const int rem = cid & 255;
    const int tm = ((sup & 3) << 4) | (rem & 15);
    const int tn = ((sup >> 2) << 4) | (rem >> 4);

    int acc1[4][4][4], acc2[4][4][4];
    #pragma unroll
    for (int a = 0; a < 4; a++)
        #pragma unroll
        for (int b = 0; b < 4; b++)
            #pragma unroll
            for (int c = 0; c < 4; c++) { acc1[a][b][c] = 0; acc2[a][b][c] = 0; }

    const char* gsrc[6];
    uint32_t doff[6];
    #pragma unroll
    for (int j = 0; j < 6; j++) {
        int id = j * 256 + tid;
        int mat = id >> 9;           // 0=X1, 1=X2, 2=B
        int r2 = id & 511;
        int row = r2 >> 2;
        int c16 = r2 & 3;
        if (mat == 0)
            gsrc[j] = (const char*)g_Ad + (size_t)(tm * BM + row) * (3 * K_IN) + c16 * 16;
        else if (mat == 1)
            gsrc[j] = (const char*)g_Ad + (size_t)(tm * BM + row) * (3 * K_IN) + K_IN + c16 * 16;
        else
            gsrc[j] = (const char*)g_Bq + (size_t)(tn * BN + row) * K_IN + c16 * 16;
        doff[j] = (uint32_t)(mat * MATB + row * 64 + SWZ(row, c16));
    }
    const uint32_t base_u[2] = { smem_u32(sbuf[0]), smem_u32(sbuf[1]) };

    #pragma unroll
    for (int j = 0; j < 6; j++) CP_ASYNC16(base_u[0] + doff[j], gsrc[j]);
    CP_COMMIT();

    for (int i = 0; i < NCH; i++) {
        const int b = i & 1;
        if (i + 1 < NCH) {
            const int nb = (i + 1) & 1;
            const size_t ko = (size_t)(i + 1) * BKB;
            #pragma unroll
            for (int j = 0; j < 6; j++)
                CP_ASYNC16(base_u[nb] + doff[j], gsrc[j] + ko);
            CP_COMMIT();
            CP_WAIT1();
        } else {
            CP_WAIT0();
        }
        __syncthreads();

        const uint32_t sA1 = base_u[b];
        const uint32_t sA2 = base_u[b] + MATB;
        const uint32_t sB  = base_u[b] + 2 * MATB;

        #pragma unroll
        for (int ks = 0; ks < 2; ks++) {
            uint32_t bf[4][2];
            #pragma unroll
            for (int g = 0; g < 2; g++) {
                const int brow = wn * 32 + g * 16 + ((lane >> 4) << 3) + (lane & 7);
                const int bc16 = ks * 2 + ((lane >> 3) & 1);
                uint32_t r[4];
                ldm_x4(r, sB + (uint32_t)(brow * 64 + SWZ(brow, bc16)));
                bf[2 * g][0] = r[0]; bf[2 * g][1] = r[1];
                bf[2 * g + 1][0] = r[2]; bf[2 * g + 1][1] = r[3];
            }
            #pragma unroll
            for (int mt = 0; mt < 4; mt++) {
                const int arow = wm * 64 + mt * 16 + (lane & 15);
                const int ac16 = ks * 2 + (lane >> 4);
                const uint32_t aoff = (uint32_t)(arow * 64 + SWZ(arow, ac16));
                uint32_t a1[4], a2[4];
                ldm_x4(a1, sA1 + aoff);
                ldm_x4(a2, sA2 + aoff);
                #pragma unroll
                for (int nt = 0; nt < 4; nt++) {
                    imma(acc1[mt][nt], a1, bf[nt][0], bf[nt][1]);
                    imma(acc2[mt][nt], a2, bf[nt][0], bf[nt][1]);
                }
            }
        }
        __syncthreads();
    }

    // epilogue: g_G = s*sn*G1 + s*s2*G2
    const float s = g_scale;
    const int rbase = tm * BM + wm * 64 + (lane >> 2);
    const int cbase = tn * BN + wn * 32 + 2 * (lane & 3);
    #pragma unroll
    for (int mt = 0; mt < 4; mt++) {
        const int r0 = rbase + mt * 16;
        const int r1 = r0 + 8;
        const float f10 = s * g_sn[r0];
        const float f20 = f10 * INV254;
        const float f11 = s * g_sn[r1];
        const float f21 = f11 * INV254;
        #pragma unroll
        for (int nt = 0; nt < 4; nt++) {
            const int cc = cbase + nt * 8;
            float2 v0, v1;
            v0.x = fmaf(f10, (float)acc1[mt][nt][0], f20 * (float)acc2[mt][nt][0]);
            v0.y = fmaf(f10, (float)acc1[mt][nt][1], f20 * (float)acc2[mt][nt][1]);
            v1.x = fmaf(f11, (float)acc1[mt][nt][2], f21 * (float)acc2[mt][nt][2]);
            v1.y = fmaf(f11, (float)acc1[mt][nt][3], f21 * (float)acc2[mt][nt][3]);
            *(float2*)&g_G[(size_t)r0 * FOUT + cc] = v0;
            *(float2*)&g_G[(size_t)r1 * FOUT + cc] = v1;
        }
    }
}

// ------- GEMM kernel 2: digit 3.  g_G += s*s3*G3; fused BN stats partials -------
__global__ void __launch_bounds__(256) gemm_imma1() {
    __shared__ char sbuf[2][2][MATB];    // [stage][X3|B] = 32 KB
    __shared__ float red[8][4][16];      // cross-warp stats reduction (2 KB)

    const int tid = threadIdx.x;
    const int wid = tid >> 5;
    const int lane = tid & 31;
    const int wm = wid & 1;
    const int wn = wid >> 1;

    const int cid = blockIdx.x;
    const int sup = cid >> 8;
    const int rem = cid & 255;
    const int tm = ((sup & 3) << 4) | (rem & 15);
    const int tn = ((sup >> 2) << 4) | (rem >> 4);

    int acc3[4][4][4];
    #pragma unroll
    for (int a = 0; a < 4; a++)
        #pragma unroll
        for (int b = 0; b < 4; b++)
            #pragma unroll
            for (int c = 0; c < 4; c++) acc3[a][b][c] = 0;

    // 1024 chunks per stage, 4 per thread
    const char* gsrc[4];
    uint32_t doff[4];
    #pragma unroll
    for (int j = 0; j < 4; j++) {
        int id = j * 256 + tid;
        int mat = id >> 9;           // 0=X3, 1=B
        int r2 = id & 511;
        int row = r2 >> 2;
        int c16 = r2 & 3;
        if (mat == 0)
            gsrc[j] = (const char*)g_Ad + (size_t)(tm * BM + row) * (3 * K_IN) + 2 * K_IN + c16 * 16;
        else
            gsrc[j] = (const char*)g_Bq + (size_t)(tn * BN + row) * K_IN + c16 * 16;
        doff[j] = (uint32_t)(mat * MATB + row * 64 + SWZ(row, c16));
    }
    const uint32_t base_u[2] = { smem_u32(sbuf[0]), smem_u32(sbuf[1]) };

    #pragma unroll
    for (int j = 0; j < 4; j++) CP_ASYNC16(base_u[0] + doff[j], gsrc[j]);
    CP_COMMIT();

    for (int i = 0; i < NCH; i++) {
        const int b = i & 1;
        if (i + 1 < NCH) {
            const int nb = (i + 1) & 1;
            const size_t ko = (size_t)(i + 1) * BKB;
            #pragma unroll
            for (int j = 0; j < 4; j++)
                CP_ASYNC16(base_u[nb] + doff[j], gsrc[j] + ko);
            CP_COMMIT();
            CP_WAIT1();
        } else {
            CP_WAIT0();
        }
        __syncthreads();

        const uint32_t sA3 = base_u[b];
        const uint32_t sB  = base_u[b] + MATB;

        #pragma unroll
        for (int ks = 0; ks < 2; ks++) {
            uint32_t bf[4][2];
            #pragma unroll
            for (int g = 0; g < 2; g++) {
                const int brow = wn * 32 + g * 16 + ((lane >> 4) << 3) + (lane & 7);
                const int bc16 = ks * 2 + ((lane >> 3) & 1);
                uint32_t r[4];
                ldm_x4(r, sB + (uint32_t)(brow * 64 + SWZ(brow, bc16)));
                bf[2 * g][0] = r[0]; bf[2 * g][1] = r[1];
                bf[2 * g + 1][0] = r[2]; bf[2 * g + 1][1] = r[3];
            }
            #pragma unroll
            for (int mt = 0; mt < 4; mt++) {
                const int arow = wm * 64 + mt * 16 + (lane & 15);
                const int ac16 = ks * 2 + (lane >> 4);
                uint32_t a3[4];
                ldm_x4(a3, sA3 + (uint32_t)(arow * 64 + SWZ(arow, ac16)));
                #pragma unroll
                for (int nt = 0; nt < 4; nt++)
                    imma(acc3[mt][nt], a3, bf[nt][0], bf[nt][1]);
            }
        }
        __syncthreads();
    }

    // epilogue: g_G += s*s3*G3, with fused per-CTA column sum/sumsq
    const float s = g_scale;
    const int rbase = tm * BM + wm * 64 + (lane >> 2);
    const int cbase = tn * BN + wn * 32 + 2 * (lane & 3);
    float cs[4][2], cq[4][2];
    #pragma unroll
    for (int nt = 0; nt < 4; nt++) {
        cs[nt][0] = 0.f; cs[nt][1] = 0.f;
        cq[nt][0] = 0.f; cq[nt][1] = 0.f;
    }
    #pragma unroll
    for (int mt = 0; mt < 4; mt++) {
        const int r0 = rbase + mt * 16;
        const int r1 = r0 + 8;
        const float f30 = ((s * g_sn[r0]) * INV254) * INV254;
        const float f31 = ((s * g_sn[r1]) * INV254) * INV254;
        #pragma unroll
        for (int nt = 0; nt < 4; nt++) {
            const int cc = cbase + nt * 8;
            float2 v0 = *(float2*)&g_G[(size_t)r0 * FOUT + cc];
            float2 v1 = *(float2*)&g_G[(size_t)r1 * FOUT + cc];
            v0.x = fmaf(f30, (float)acc3[mt][nt][0], v0.x);
            v0.y = fmaf(f30, (float)acc3[mt][nt][1], v0.y);
            v1.x = fmaf(f31, (float)acc3[mt][nt][2], v1.x);
            v1.y = fmaf(f31, (float)acc3[mt][nt][3], v1.y);
            *(float2*)&g_G[(size_t)r0 * FOUT + cc] = v0;
            *(float2*)&g_G[(size_t)r1 * FOUT + cc] = v1;
            cs[nt][0] += v0.x + v1.x;   cs[nt][1] += v0.y + v1.y;
            cq[nt][0] = fmaf(v0.x, v0.x, fmaf(v1.x, v1.x, cq[nt][0]));
            cq[nt][1] = fmaf(v0.y, v0.y, fmaf(v1.y, v1.y, cq[nt][1]));
        }
    }
    // reduce over the 8 threads (stride 4) sharing the same columns
    #pragma unroll
    for (int o = 16; o >= 4; o >>= 1) {
        #pragma unroll
        for (int nt = 0; nt < 4; nt++) {
            cs[nt][0] += __shfl_down_sync(0xffffffffu, cs[nt][0], o);
            cs[nt][1] += __shfl_down_sync(0xffffffffu, cs[nt][1], o);
            cq[nt][0] += __shfl_down_sync(0xffffffffu, cq[nt][0], o);
            cq[nt][1] += __shfl_down_sync(0xffffffffu, cq[nt][1], o);
        }
    }
    if (lane < 4) {
        #pragma unroll
        for (int nt = 0; nt < 4; nt++) {
            red[wid][lane][nt * 2]     = cs[nt][0];
            red[wid][lane][nt * 2 + 1] = cs[nt][1];
            red[wid][lane][8 + nt * 2]     = cq[nt][0];
            red[wid][lane][8 + nt * 2 + 1] = cq[nt][1];
        }
    }
    __syncthreads();
    if (wm == 0 && lane < 4) {
        const int col0 = tn * BN + wn * 32 + 2 * lane;
        #pragma unroll
        for (int nt = 0; nt < 4; nt++) {
            #pragma unroll
            for (int h = 0; h < 2; h++) {
                float ssum = red[wid][lane][nt * 2 + h] + red[wid + 1][lane][nt * 2 + h];
                float qsum = red[wid][lane][8 + nt * 2 + h] + red[wid + 1][lane][8 + nt * 2 + h];
                g_psum2[tm][col0 + nt * 8 + h] = ssum;
                g_psq2[tm][col0 + nt * 8 + h] = qsum;
            }
        }
    }
}

// ---------------- coef + BN + act-quant ----------------
__global__ void coef_kernel(int Nr, int Nc) {
    int c = blockIdx.x * blockDim.x + threadIdx.x;
    if (c >= Nc) return;
    float s = 0.f, q = 0.f;
    #pragma unroll 8
    for (int i = 0; i < MT; i++) { s += g_psum2[i][c]; q += g_psq2[i][c]; }
    float mean = s / (float)Nr;
    float ex2  = q / (float)Nr;
    float var  = ex2 - mean * mean;
    g_mean[c] = mean;
    g_rstd[c] = (float)(1.0 / sqrt((double)var + 1e-5));
}

// Vectorized BN + activation quantization (float4; FOUT % 4 == 0)
__global__ void bnq_kernel(const float* __restrict__ gamma,
                           const float* __restrict__ beta,
                           const int* __restrict__ abits,
                           float* __restrict__ out, int total4) {
    float na = (float)((1 << (*abits)) - 1);
    for (int i = blockIdx.x * blockDim.x + threadIdx.x; i < total4;
         i += gridDim.x * blockDim.x) {
        int c = (i << 2) & (FOUT - 1);
        float4 g  = ((const float4*)g_G)[i];
        float4 ga = *(const float4*)&gamma[c];
        float4 be = *(const float4*)&beta[c];
        float4 mu = *(const float4*)&g_mean[c];
        float4 rs = *(const float4*)&g_rstd[c];
        float4 r;
        {
            float y = ga.x * (g.x - mu.x) * rs.x + be.x;
            float yc = fminf(fmaxf(y, 0.f), 1.f);
            r.x = yc + (__fdiv_rn(rintf(yc * na), na) - yc);
        }
        {
            float y = ga.y * (g.y - mu.y) * rs.y + be.y;
            float yc = fminf(fmaxf(y, 0.f), 1.f);
            r.y = yc + (__fdiv_rn(rintf(yc * na), na) - yc);
        }
        {
            float y = ga.z * (g.z - mu.z) * rs.z + be.z;
            float yc = fminf(fmaxf(y, 0.f), 1.f);
            r.z = yc + (__fdiv_rn(rintf(yc * na), na) - yc);
        }
        {
            float y = ga.w * (g.w - mu.w) * rs.w + be.w;
            float yc = fminf(fmaxf(y, 0.f), 1.f);
            r.w = yc + (__fdiv_rn(rintf(yc * na), na) - yc);
        }
        ((float4*)out)[i] = r;
    }
}

// ---------------- launch ----------------
extern "C" void kernel_launch(void* const* d_in, const int* in_sizes, int n_in,
                              void* d_out, int out_size) {
    const float* x     = (const float*)d_in[0];
    const float* W     = (const float*)d_in[1];
    const float* gamma = (const float*)d_in[2];
    const float* beta  = (const float*)d_in[3];
    const int*   wbits = (const int*)d_in[4];
    const int*   abits = (const int*)d_in[5];

    init_kernel<<<1, 32>>>();
    maxabs_kernel<<<256, 256>>>(W, FOUT * K_IN);
    scale_kernel<<<1, 1>>>(wbits);
    quantm_kernel<<<(FOUT * K_IN / 4) / 256, 256>>>(W, wbits);
    rowdig_kernel<<<NROW, 256>>>(x);

    gemm_imma2<<<MT * NT, 256>>>();
    gemm_imma1<<<MT * NT, 256>>>();

    coef_kernel<<<(FOUT + 255) / 256, 256>>>(NROW, FOUT);
    bnq_kernel<<<2048, 256>>>(gamma, beta, abits, (float*)d_out,
                              NROW * FOUT / 4);
}

// round 16
// speedup vs baseline: 1.1409x; 1.0055x over previous
#include <cuda_runtime.h>
#include <math.h>
#include <stdint.h>

// Fixed problem shape (verified R1: x[8192,4096], W[4096,4096])
#define K_IN 4096
#define NROW 8192
#define FOUT 4096

#define BM 128
#define BN 128
#define BKB 64                // K bytes per stage (64 int8)
#define NCH (K_IN / BKB)      // 64
#define MT (NROW / BM)        // 64
#define NT (FOUT / BN)        // 32
#define MATB (BM * 64)        // 8192 B per matrix per stage
#define INV254 (1.f / 254.f)

// XOR swizzle: 16B-chunk index within a 64B row, keyed by row
#define SWZ(row, c16) (((c16) ^ (((row) >> 1) & 3)) << 4)

// ---------------- device scratch ----------------
__device__ int8_t g_Ad[(size_t)NROW * (3 * K_IN)];  // [X1 | X2 | X3] per row
__device__ int8_t g_Bq[(size_t)FOUT * K_IN];        // weight codes m
__device__ float g_G[(size_t)NROW * FOUT];
__device__ float g_sn[NROW];                        // per-row scale s_n
__device__ unsigned int g_maxbits;                  // zero at module load; self-reset
__device__ float g_scale;
__device__ float g_psum2[MT][FOUT];                 // per-row-block partial sums
__device__ float g_psq2[MT][FOUT];
__device__ float g_mean[FOUT];
__device__ float g_rstd[FOUT];

// ---------------- helpers (sm_80-era PTX: legal at compute_100) ----------------
__device__ __forceinline__ uint32_t smem_u32(const void* p) {
    return (uint32_t)__cvta_generic_to_shared(p);
}
#define CP_ASYNC16(dst, src) \
    asm volatile("cp.async.cg.shared.global [%0], [%1], 16;" :: "r"(dst), "l"(src) : "memory")
#define CP_COMMIT() asm volatile("cp.async.commit_group;" ::: "memory")
#define CP_WAIT1()  asm volatile("cp.async.wait_group 1;" ::: "memory")
#define CP_WAIT0()  asm volatile("cp.async.wait_group 0;" ::: "memory")

__device__ __forceinline__ void ldm_x4(uint32_t* r, uint32_t addr) {
    asm volatile("ldmatrix.sync.aligned.m8n8.x4.shared.b16 {%0,%1,%2,%3}, [%4];"
                 : "=r"(r[0]), "=r"(r[1]), "=r"(r[2]), "=r"(r[3]) : "r"(addr));
}
__device__ __forceinline__ void imma(int* d, const uint32_t* a, uint32_t b0, uint32_t b1) {
    asm volatile(
        "mma.sync.aligned.m16n8k32.row.col.s32.s8.s8.s32 "
        "{%0,%1,%2,%3}, {%4,%5,%6,%7}, {%8,%9}, {%0,%1,%2,%3};"
        : "+r"(d[0]), "+r"(d[1]), "+r"(d[2]), "+r"(d[3])
        : "r"(a[0]), "r"(a[1]), "r"(a[2]), "r"(a[3]), "r"(b0), "r"(b1));
}

// ---------------- small kernels ----------------
__global__ void maxabs_kernel(const float* __restrict__ W, int n) {
    float m = 0.f;
    for (int i = blockIdx.x * blockDim.x + threadIdx.x; i < n;
         i += gridDim.x * blockDim.x)
        m = fmaxf(m, fabsf(W[i]));
    #pragma unroll
    for (int o = 16; o > 0; o >>= 1)
        m = fmaxf(m, __shfl_xor_sync(0xffffffffu, m, o));
    if ((threadIdx.x & 31) == 0)
        atomicMax(&g_maxbits, __float_as_uint(m));
}

// Reads the max, computes the per-tensor scale, then resets the accumulator
// so the next graph replay starts clean (module-load zero covers call #1).
__global__ void scale_kernel(const int* __restrict__ wbits) {
    float nf = (float)((1 << ((*wbits) - 1)) - 1);
    g_scale = __fdiv_rn(__uint_as_float(g_maxbits), nf);
    g_maxbits = 0u;
}

// W -> integer codes m (int8)
__global__ void quantm_kernel(const float* __restrict__ W,
                              const int* __restrict__ wbits) {
    float s = g_scale;
    float nf = (float)((1 << ((*wbits) - 1)) - 1);
    int t = blockIdx.x * blockDim.x + threadIdx.x;   // over FOUT*K_IN/4
    float4 w = ((const float4*)W)[t];
    float m0 = fminf(fmaxf(rintf(__fdiv_rn(w.x, s)), -nf), nf);
    float m1 = fminf(fmaxf(rintf(__fdiv_rn(w.y, s)), -nf), nf);
    float m2 = fminf(fmaxf(rintf(__fdiv_rn(w.z, s)), -nf), nf);
    float m3 = fminf(fmaxf(rintf(__fdiv_rn(w.w, s)), -nf), nf);
    char4 c = make_char4((char)(int)m0, (char)(int)m1, (char)(int)m2, (char)(int)m3);
    *(char4*)&g_Bq[(size_t)t * 4] = c;
}

// Fused: per-row max + 3-digit int8 encoding (row stays in registers)
__global__ void rowdig_kernel(const float* __restrict__ x) {
    __shared__ float red[8];
    __shared__ float bc[2];
    const int row = blockIdx.x;
    const int tid = threadIdx.x;
    const float4* p = (const float4*)(x + (size_t)row * K_IN);
    float4 v[4];
    float m = 0.f;
    #pragma unroll
    for (int i = 0; i < 4; i++) {
        v[i] = p[tid + i * 256];
        m = fmaxf(m, fmaxf(fmaxf(fabsf(v[i].x), fabsf(v[i].y)),
                           fmaxf(fabsf(v[i].z), fabsf(v[i].w))));
    }
    #pragma unroll
    for (int o = 16; o > 0; o >>= 1)
        m = fmaxf(m, __shfl_xor_sync(0xffffffffu, m, o));
    if ((tid & 31) == 0) red[tid >> 5] = m;
    __syncthreads();
    if (tid == 0) {
        float mm = red[0];
        #pragma unroll
        for (int i = 1; i < 8; i++) mm = fmaxf(mm, red[i]);
        float sn = __fdiv_rn(mm, 127.f);
        float inv = __fdiv_rn(127.f, mm);
        g_sn[row] = sn;
        bc[0] = sn; bc[1] = inv;
    }
    __syncthreads();
    const float sn = bc[0];
    const float inv = bc[1];
    const float s2 = sn * INV254;
    const float inv2 = inv * 254.f;
    const float inv3 = inv2 * 254.f;
    #pragma unroll
    for (int i = 0; i < 4; i++) {
        const int col = (tid + i * 256) * 4;
        float e[4] = {v[i].x, v[i].y, v[i].z, v[i].w};
        float X1[4], X2[4], X3[4];
        #pragma unroll
        for (int j = 0; j < 4; j++) {
            float d1 = fminf(fmaxf(rintf(e[j] * inv), -127.f), 127.f);
            float r1 = fmaf(-d1, sn, e[j]);
            float d2 = fminf(fmaxf(rintf(r1 * inv2), -127.f), 127.f);
            float r2 = fmaf(-d2, s2, r1);
            float d3 = fminf(fmaxf(rintf(r2 * inv3), -127.f), 127.f);
            X1[j] = d1; X2[j] = d2; X3[j] = d3;
        }
        char4 c1 = make_char4((char)(int)X1[0], (char)(int)X1[1],
                              (char)(int)X1[2], (char)(int)X1[3]);
        char4 c2 = make_char4((char)(int)X2[0], (char)(int)X2[1],
                              (char)(int)X2[2], (char)(int)X2[3]);
        char4 c3 = make_char4((char)(int)X3[0], (char)(int)X3[1],
                              (char)(int)X3[2], (char)(int)X3[3]);
        *(char4*)&g_Ad[(size_t)row * (3 * K_IN) + col] = c1;
        *(char4*)&g_Ad[(size_t)row * (3 * K_IN) + K_IN + col] = c2;
        *(char4*)&g_Ad[(size_t)row * (3 * K_IN) + 2 * K_IN + col] = c3;
    }
}

// ------- GEMM kernel 1: digits 1+2.  g_G = s*(sn*G1 + s2*G2) -------
// Tiles traversed in REVERSE so Ad (just written forward) is read newest-first
// (L2 hits), and G writes end at low addresses for k2's forward reads.
__global__ void __launch_bounds__(256) gemm_imma2() {
    __shared__ char sbuf[2][3][MATB];    // [stage][X1|X2|B] = 48 KB

    const int tid = threadIdx.x;
    const int wid = tid >> 5;
    const int lane = tid & 31;
    const int wm = wid & 1;
    const int wn = wid >> 1;

    const int cid = (MT * NT - 1) - blockIdx.x;   // reverse raster
    const int sup = cid >> 8;
    const int rem = cid & 255;
    const int tm = ((sup & 3) << 4) | (rem & 15);
    const int tn = ((sup >> 2) << 4) | (rem >> 4);

    int acc1[4][4][4], acc2[4][4][4];
    #pragma unroll
    for (int a = 0; a < 4; a++)
        #pragma unroll
        for (int b = 0; b < 4; b++)
            #pragma unroll
            for (int c = 0; c < 4; c++) { acc1[a][b][c] = 0; acc2[a][b][c] = 0; }

    const char* gsrc[6];
    uint32_t doff[6];
    #pragma unroll
    for (int j = 0; j < 6; j++) {
        int id = j * 256 + tid;
        int mat = id >> 9;           // 0=X1, 1=X2, 2=B
        int r2 = id & 511;
        int row = r2 >> 2;
        int c16 = r2 & 3;
        if (mat == 0)
            gsrc[j] = (const char*)g_Ad + (size_t)(tm * BM + row) * (3 * K_IN) + c16 * 16;
        else if (mat == 1)
            gsrc[j] = (const char*)g_Ad + (size_t)(tm * BM + row) * (3 * K_IN) + K_IN + c16 * 16;
        else
            gsrc[j] = (const char*)g_Bq + (size_t)(tn * BN + row) * K_IN + c16 * 16;
        doff[j] = (uint32_t)(mat * MATB + row * 64 + SWZ(row, c16));
    }
    const uint32_t base_u[2] = { smem_u32(sbuf[0]), smem_u32(sbuf[1]) };

    #pragma unroll
    for (int j = 0; j < 6; j++) CP_ASYNC16(base_u[0] + doff[j], gsrc[j]);
    CP_COMMIT();

    for (int i = 0; i < NCH; i++) {
        const int b = i & 1;
        if (i + 1 < NCH) {
            const int nb = (i + 1) & 1;
            const size_t ko = (size_t)(i + 1) * BKB;
            #pragma unroll
            for (int j = 0; j < 6; j++)
                CP_ASYNC16(base_u[nb] + doff[j], gsrc[j] + ko);
            CP_COMMIT();
            CP_WAIT1();
        } else {
            CP_WAIT0();
        }
        __syncthreads();

        const uint32_t sA1 = base_u[b];
        const uint32_t sA2 = base_u[b] + MATB;
        const uint32_t sB  = base_u[b] + 2 * MATB;

        #pragma unroll
        for (int ks = 0; ks < 2; ks++) {
            uint32_t bf[4][2];
            #pragma unroll
            for (int g = 0; g < 2; g++) {
                const int brow = wn * 32 + g * 16 + ((lane >> 4) << 3) + (lane & 7);
                const int bc16 = ks * 2 + ((lane >> 3) & 1);
                uint32_t r[4];
                ldm_x4(r, sB + (uint32_t)(brow * 64 + SWZ(brow, bc16)));
                bf[2 * g][0] = r[0]; bf[2 * g][1] = r[1];
                bf[2 * g + 1][0] = r[2]; bf[2 * g + 1][1] = r[3];
            }
            #pragma unroll
            for (int mt = 0; mt < 4; mt++) {
                const int arow = wm * 64 + mt * 16 + (lane & 15);
                const int ac16 = ks * 2 + (lane >> 4);
                const uint32_t aoff = (uint32_t)(arow * 64 + SWZ(arow, ac16));
                uint32_t a1[4], a2[4];
                ldm_x4(a1, sA1 + aoff);
                ldm_x4(a2, sA2 + aoff);
                #pragma unroll
                for (int nt = 0; nt < 4; nt++) {
                    imma(acc1[mt][nt], a1, bf[nt][0], bf[nt][1]);
                    imma(acc2[mt][nt], a2, bf[nt][0], bf[nt][1]);
                }
            }
        }
        __syncthreads();
    }

    // epilogue: g_G = s*sn*G1 + s*s2*G2
    const float s = g_scale;
    const int rbase = tm * BM + wm * 64 + (lane >> 2);
    const int cbase = tn * BN + wn * 32 + 2 * (lane & 3);
    #pragma unroll
    for (int mt = 0; mt < 4; mt++) {
        const int r0 = rbase + mt * 16;
        const int r1 = r0 + 8;
        const float f10 = s * g_sn[r0];
        const float f20 = f10 * INV254;
        const float f11 = s * g_sn[r1];
        const float f21 = f11 * INV254;
        #pragma unroll
        for (int nt = 0; nt < 4; nt++) {
            const int cc = cbase + nt * 8;
            float2 v0, v1;
            v0.x = fmaf(f10, (float)acc1[mt][nt][0], f20 * (float)acc2[mt][nt][0]);
            v0.y = fmaf(f10, (float)acc1[mt][nt][1], f20 * (float)acc2[mt][nt][1]);
            v1.x = fmaf(f11, (float)acc1[mt][nt][2], f21 * (float)acc2[mt][nt][2]);
            v1.y = fmaf(f11, (float)acc1[mt][nt][3], f21 * (float)acc2[mt][nt][3]);
            *(float2*)&g_G[(size_t)r0 * FOUT + cc] = v0;
            *(float2*)&g_G[(size_t)r1 * FOUT + cc] = v1;
        }
    }
}

// ------- GEMM kernel 2: digit 3.  g_G += s*s3*G3; fused BN stats partials -------
// FORWARD raster: first tiles read are k1's freshest (low-address) G writes.
__global__ void __launch_bounds__(256) gemm_imma1() {
    __shared__ char sbuf[2][2][MATB];    // [stage][X3|B] = 32 KB
    __shared__ float red[8][4][16];      // cross-warp stats reduction (2 KB)

    const int tid = threadIdx.x;
    const int wid = tid >> 5;
    const int lane = tid & 31;
    const int wm = wid & 1;
    const int wn = wid >> 1;

    const int cid = blockIdx.x;
    const int sup = cid >> 8;
    const int rem = cid & 255;
    const int tm = ((sup & 3) << 4) | (rem & 15);
    const int tn = ((sup >> 2) << 4) | (rem >> 4);

    int acc3[4][4][4];
    #pragma unroll
    for (int a = 0; a < 4; a++)
        #pragma unroll
        for (int b = 0; b < 4; b++)
            #pragma unroll
            for (int c = 0; c < 4; c++) acc3[a][b][c] = 0;

    // 1024 chunks per stage, 4 per thread
    const char* gsrc[4];
    uint32_t doff[4];
    #pragma unroll
    for (int j = 0; j < 4; j++) {
        int id = j * 256 + tid;
        int mat = id >> 9;           // 0=X3, 1=B
        int r2 = id & 511;
        int row = r2 >> 2;
        int c16 = r2 & 3;
        if (mat == 0)
            gsrc[j] = (const char*)g_Ad + (size_t)(tm * BM + row) * (3 * K_IN) + 2 * K_IN + c16 * 16;
        else
            gsrc[j] = (const char*)g_Bq + (size_t)(tn * BN + row) * K_IN + c16 * 16;
        doff[j] = (uint32_t)(mat * MATB + row * 64 + SWZ(row, c16));
    }
    const uint32_t base_u[2] = { smem_u32(sbuf[0]), smem_u32(sbuf[1]) };

    #pragma unroll
    for (int j = 0; j < 4; j++) CP_ASYNC16(base_u[0] + doff[j], gsrc[j]);
    CP_COMMIT();

    for (int i = 0; i < NCH; i++) {
        const int b = i & 1;
        if (i + 1 < NCH) {
            const int nb = (i + 1) & 1;
            const size_t ko = (size_t)(i + 1) * BKB;
            #pragma unroll
            for (int j = 0; j < 4; j++)
                CP_ASYNC16(base_u[nb] + doff[j], gsrc[j] + ko);
            CP_COMMIT();
            CP_WAIT1();
        } else {
            CP_WAIT0();
        }
        __syncthreads();

        const uint32_t sA3 = base_u[b];
        const uint32_t sB  = base_u[b] + MATB;

        #pragma unroll
        for (int ks = 0; ks < 2; ks++) {
            uint32_t bf[4][2];
            #pragma unroll
            for (int g = 0; g < 2; g++) {
                const int brow = wn * 32 + g * 16 + ((lane >> 4) << 3) + (lane & 7);
                const int bc16 = ks * 2 + ((lane >> 3) & 1);
                uint32_t r[4];
                ldm_x4(r, sB + (uint32_t)(brow * 64 + SWZ(brow, bc16)));
                bf[2 * g][0] = r[0]; bf[2 * g][1] = r[1];
                bf[2 * g + 1][0] = r[2]; bf[2 * g + 1][1] = r[3];
            }
            #pragma unroll
            for (int mt = 0; mt < 4; mt++) {
                const int arow = wm * 64 + mt * 16 + (lane & 15);
                const int ac16 = ks * 2 + (lane >> 4);
                uint32_t a3[4];
                ldm_x4(a3, sA3 + (uint32_t)(arow * 64 + SWZ(arow, ac16)));
                #pragma unroll
                for (int nt = 0; nt < 4; nt++)
                    imma(acc3[mt][nt], a3, bf[nt][0], bf[nt][1]);
            }
        }
        __syncthreads();
    }

    // epilogue: g_G += s*s3*G3, with fused per-CTA column sum/sumsq
    const float s = g_scale;
    const int rbase = tm * BM + wm * 64 + (lane >> 2);
    const int cbase = tn * BN + wn * 32 + 2 * (lane & 3);
    float cs[4][2], cq[4][2];
    #pragma unroll
    for (int nt = 0; nt < 4; nt++) {
        cs[nt][0] = 0.f; cs[nt][1] = 0.f;
        cq[nt][0] = 0.f; cq[nt][1] = 0.f;
    }
    #pragma unroll
    for (int mt = 0; mt < 4; mt++) {
        const int r0 = rbase + mt * 16;
        const int r1 = r0 + 8;
        const float f30 = ((s * g_sn[r0]) * INV254) * INV254;
        const float f31 = ((s * g_sn[r1]) * INV254) * INV254;
        #pragma unroll
        for (int nt = 0; nt < 4; nt++) {
            const int cc = cbase + nt * 8;
            float2 v0 = *(float2*)&g_G[(size_t)r0 * FOUT + cc];
            float2 v1 = *(float2*)&g_G[(size_t)r1 * FOUT + cc];
            v0.x = fmaf(f30, (float)acc3[mt][nt][0], v0.x);
            v0.y = fmaf(f30, (float)acc3[mt][nt][1], v0.y);
            v1.x = fmaf(f31, (float)acc3[mt][nt][2], v1.x);
            v1.y = fmaf(f31, (float)acc3[mt][nt][3], v1.y);
            *(float2*)&g_G[(size_t)r0 * FOUT + cc] = v0;
            *(float2*)&g_G[(size_t)r1 * FOUT + cc] = v1;
            cs[nt][0] += v0.x + v1.x;   cs[nt][1] += v0.y + v1.y;
            cq[nt][0] = fmaf(v0.x, v0.x, fmaf(v1.x, v1.x, cq[nt][0]));
            cq[nt][1] = fmaf(v0.y, v0.y, fmaf(v1.y, v1.y, cq[nt][1]));
        }
    }
    // reduce over the 8 threads (stride 4) sharing the same columns
    #pragma unroll
    for (int o = 16; o >= 4; o >>= 1) {
        #pragma unroll
        for (int nt = 0; nt < 4; nt++) {
            cs[nt][0] += __shfl_down_sync(0xffffffffu, cs[nt][0], o);
            cs[nt][1] += __shfl_down_sync(0xffffffffu, cs[nt][1], o);
            cq[nt][0] += __shfl_down_sync(0xffffffffu, cq[nt][0], o);
            cq[nt][1] += __shfl_down_sync(0xffffffffu, cq[nt][1], o);
        }
    }
    if (lane < 4) {
        #pragma unroll
        for (int nt = 0; nt < 4; nt++) {
            red[wid][lane][nt * 2]     = cs[nt][0];
            red[wid][lane][nt * 2 + 1] = cs[nt][1];
            red[wid][lane][8 + nt * 2]     = cq[nt][0];
            red[wid][lane][8 + nt * 2 + 1] = cq[nt][1];
        }
    }
    __syncthreads();
    if (wm == 0 && lane < 4) {
        const int col0 = tn * BN + wn * 32 + 2 * lane;
        #pragma unroll
        for (int nt = 0; nt < 4; nt++) {
            #pragma unroll
            for (int h = 0; h < 2; h++) {
                float ssum = red[wid][lane][nt * 2 + h] + red[wid + 1][lane][nt * 2 + h];
                float qsum = red[wid][lane][8 + nt * 2 + h] + red[wid + 1][lane][8 + nt * 2 + h];
                g_psum2[tm][col0 + nt * 8 + h] = ssum;
                g_psq2[tm][col0 + nt * 8 + h] = qsum;
            }
        }
    }
}

// ---------------- coef + BN + act-quant ----------------
__global__ void coef_kernel(int Nr, int Nc) {
    int c = blockIdx.x * blockDim.x + threadIdx.x;
    if (c >= Nc) return;
    float s = 0.f, q = 0.f;
    #pragma unroll 8
    for (int i = 0; i < MT; i++) { s += g_psum2[i][c]; q += g_psq2[i][c]; }
    float mean = s / (float)Nr;
    float ex2  = q / (float)Nr;
    float var  = ex2 - mean * mean;
    g_mean[c] = mean;
    g_rstd[c] = (float)(1.0 / sqrt((double)var + 1e-5));
}

// Vectorized BN + activation quantization (float4), iterating in REVERSE so
// the first reads hit k2's freshest (high-address) G tiles in L2.
__global__ void bnq_kernel(const float* __restrict__ gamma,
                           const float* __restrict__ beta,
                           const int* __restrict__ abits,
                           float* __restrict__ out, int total4) {
    float na = (float)((1 << (*abits)) - 1);
    for (int i = blockIdx.x * blockDim.x + threadIdx.x; i < total4;
         i += gridDim.x * blockDim.x) {
        int j = total4 - 1 - i;                  // reverse traversal
        int c = (j << 2) & (FOUT - 1);
        float4 g  = ((const float4*)g_G)[j];
        float4 ga = *(const float4*)&gamma[c];
        float4 be = *(const float4*)&beta[c];
        float4 mu = *(const float4*)&g_mean[c];
        float4 rs = *(const float4*)&g_rstd[c];
        float4 r;
        {
            float y = ga.x * (g.x - mu.x) * rs.x + be.x;
            float yc = fminf(fmaxf(y, 0.f), 1.f);
            r.x = yc + (__fdiv_rn(rintf(yc * na), na) - yc);
        }
        {
            float y = ga.y * (g.y - mu.y) * rs.y + be.y;
            float yc = fminf(fmaxf(y, 0.f), 1.f);
            r.y = yc + (__fdiv_rn(rintf(yc * na), na) - yc);
        }
        {
            float y = ga.z * (g.z - mu.z) * rs.z + be.z;
            float yc = fminf(fmaxf(y, 0.f), 1.f);
            r.z = yc + (__fdiv_rn(rintf(yc * na), na) - yc);
        }
        {
            float y = ga.w * (g.w - mu.w) * rs.w + be.w;
            float yc = fminf(fmaxf(y, 0.f), 1.f);
            r.w = yc + (__fdiv_rn(rintf(yc * na), na) - yc);
        }
        ((float4*)out)[j] = r;
    }
}

// ---------------- launch ----------------
extern "C" void kernel_launch(void* const* d_in, const int* in_sizes, int n_in,
                              void* d_out, int out_size) {
    const float* x     = (const float*)d_in[0];
    const float* W     = (const float*)d_in[1];
    const float* gamma = (const float*)d_in[2];
    const float* beta  = (const float*)d_in[3];
    const int*   wbits = (const int*)d_in[4];
    const int*   abits = (const int*)d_in[5];

    maxabs_kernel<<<256, 256>>>(W, FOUT * K_IN);
    scale_kernel<<<1, 1>>>(wbits);
    quantm_kernel<<<(FOUT * K_IN / 4) / 256, 256>>>(W, wbits);
    rowdig_kernel<<<NROW, 256>>>(x);

    gemm_imma2<<<MT * NT, 256>>>();
    gemm_imma1<<<MT * NT, 256>>>();

    coef_kernel<<<(FOUT + 255) / 256, 256>>>(NROW, FOUT);
    bnq_kernel<<<2048, 256>>>(gamma, beta, abits, (float*)d_out,
                              NROW * FOUT / 4);
}

// round 17
// speedup vs baseline: 1.1424x; 1.0013x over previous
#include <cuda_runtime.h>
#include <math.h>
#include <stdint.h>

// Fixed problem shape (verified R1: x[8192,4096], W[4096,4096])
#define K_IN 4096
#define NROW 8192
#define FOUT 4096

#define BM 128
#define BN 128
#define BKB 64                // K bytes per stage (64 int8)
#define NCH (K_IN / BKB)      // 64
#define MT (NROW / BM)        // 64
#define NT (FOUT / BN)        // 32
#define MATB (BM * 64)        // 8192 B per matrix per stage
#define INV254 (1.f / 254.f)

// XOR swizzle: 16B-chunk index within a 64B row, keyed by row
#define SWZ(row, c16) (((c16) ^ (((row) >> 1) & 3)) << 4)

// ---------------- device scratch ----------------
__device__ int8_t g_Ad[(size_t)NROW * (3 * K_IN)];  // [X1 | X2 | X3] per row
__device__ int8_t g_Bq[(size_t)FOUT * K_IN];        // weight codes m
__device__ float g_G[(size_t)NROW * FOUT];
__device__ float g_sn[NROW];                        // per-row scale s_n
__device__ unsigned int g_maxbits;                  // zero at module load; self-reset
__device__ float g_scale;
__device__ float g_psum2[MT][FOUT];                 // per-row-block partial sums
__device__ float g_psq2[MT][FOUT];
__device__ float g_mean[FOUT];
__device__ float g_rstd[FOUT];

// ---------------- helpers (sm_80-era PTX: legal at compute_100) ----------------
__device__ __forceinline__ uint32_t smem_u32(const void* p) {
    return (uint32_t)__cvta_generic_to_shared(p);
}
#define CP_ASYNC16(dst, src) \
    asm volatile("cp.async.cg.shared.global [%0], [%1], 16;" :: "r"(dst), "l"(src) : "memory")
#define CP_COMMIT() asm volatile("cp.async.commit_group;" ::: "memory")
#define CP_WAIT1()  asm volatile("cp.async.wait_group 1;" ::: "memory")
#define CP_WAIT0()  asm volatile("cp.async.wait_group 0;" ::: "memory")

__device__ __forceinline__ void ldm_x4(uint32_t* r, uint32_t addr) {
    asm volatile("ldmatrix.sync.aligned.m8n8.x4.shared.b16 {%0,%1,%2,%3}, [%4];"
                 : "=r"(r[0]), "=r"(r[1]), "=r"(r[2]), "=r"(r[3]) : "r"(addr));
}
__device__ __forceinline__ void imma(int* d, const uint32_t* a, uint32_t b0, uint32_t b1) {
    asm volatile(
        "mma.sync.aligned.m16n8k32.row.col.s32.s8.s8.s32 "
        "{%0,%1,%2,%3}, {%4,%5,%6,%7}, {%8,%9}, {%0,%1,%2,%3};"
        : "+r"(d[0]), "+r"(d[1]), "+r"(d[2]), "+r"(d[3])
        : "r"(a[0]), "r"(a[1]), "r"(a[2]), "r"(a[3]), "r"(b0), "r"(b1));
}

__device__ __forceinline__ uint32_t pack4(float a, float b, float c, float d) {
    char4 v = make_char4((char)(int)a, (char)(int)b, (char)(int)c, (char)(int)d);
    uint32_t u;
    memcpy(&u, &v, 4);
    return u;
}

// ---------------- small kernels ----------------
__global__ void maxabs_kernel(const float* __restrict__ W, int n) {
    float m = 0.f;
    for (int i = blockIdx.x * blockDim.x + threadIdx.x; i < n;
         i += gridDim.x * blockDim.x)
        m = fmaxf(m, fabsf(W[i]));
    #pragma unroll
    for (int o = 16; o > 0; o >>= 1)
        m = fmaxf(m, __shfl_xor_sync(0xffffffffu, m, o));
    if ((threadIdx.x & 31) == 0)
        atomicMax(&g_maxbits, __float_as_uint(m));
}

// Reads the max, computes the per-tensor scale, then resets the accumulator
// so the next graph replay starts clean (module-load zero covers call #1).
__global__ void scale_kernel(const int* __restrict__ wbits) {
    float nf = (float)((1 << ((*wbits) - 1)) - 1);
    g_scale = __fdiv_rn(__uint_as_float(g_maxbits), nf);
    g_maxbits = 0u;
}

// W -> integer codes m (int8). 16 elements/thread, one int4 store.
__global__ void quantm_kernel(const float* __restrict__ W,
                              const int* __restrict__ wbits) {
    float s = g_scale;
    float nf = (float)((1 << ((*wbits) - 1)) - 1);
    int t = blockIdx.x * blockDim.x + threadIdx.x;   // over FOUT*K_IN/16
    const float4* wp = (const float4*)W + (size_t)t * 4;
    uint32_t packed[4];
    #pragma unroll
    for (int i = 0; i < 4; i++) {
        float4 w = wp[i];
        float m0 = fminf(fmaxf(rintf(__fdiv_rn(w.x, s)), -nf), nf);
        float m1 = fminf(fmaxf(rintf(__fdiv_rn(w.y, s)), -nf), nf);
        float m2 = fminf(fmaxf(rintf(__fdiv_rn(w.z, s)), -nf), nf);
        float m3 = fminf(fmaxf(rintf(__fdiv_rn(w.w, s)), -nf), nf);
        packed[i] = pack4(m0, m1, m2, m3);
    }
    *(uint4*)&g_Bq[(size_t)t * 16] =
        make_uint4(packed[0], packed[1], packed[2], packed[3]);
}

// Fused: per-row max + 3-digit int8 encoding; 16 contiguous elements/thread,
// one 16B store per digit plane.
__global__ void rowdig_kernel(const float* __restrict__ x) {
    __shared__ float red[8];
    __shared__ float bc[2];
    const int row = blockIdx.x;
    const int tid = threadIdx.x;
    const float4* p = (const float4*)(x + (size_t)row * K_IN) + tid * 4;
    float4 v[4];
    float m = 0.f;
    #pragma unroll
    for (int i = 0; i < 4; i++) {
        v[i] = p[i];
        m = fmaxf(m, fmaxf(fmaxf(fabsf(v[i].x), fabsf(v[i].y)),
                           fmaxf(fabsf(v[i].z), fabsf(v[i].w))));
    }
    #pragma unroll
    for (int o = 16; o > 0; o >>= 1)
        m = fmaxf(m, __shfl_xor_sync(0xffffffffu, m, o));
    if ((tid & 31) == 0) red[tid >> 5] = m;
    __syncthreads();
    if (tid == 0) {
        float mm = red[0];
        #pragma unroll
        for (int i = 1; i < 8; i++) mm = fmaxf(mm, red[i]);
        float sn = __fdiv_rn(mm, 127.f);
        float inv = __fdiv_rn(127.f, mm);
        g_sn[row] = sn;
        bc[0] = sn; bc[1] = inv;
    }
    __syncthreads();
    const float sn = bc[0];
    const float inv = bc[1];
    const float s2 = sn * INV254;
    const float inv2 = inv * 254.f;
    const float inv3 = inv2 * 254.f;
    uint32_t p1[4], p2[4], p3[4];
    #pragma unroll
    for (int i = 0; i < 4; i++) {
        float e[4] = {v[i].x, v[i].y, v[i].z, v[i].w};
        float X1[4], X2[4], X3[4];
        #pragma unroll
        for (int j = 0; j < 4; j++) {
            float d1 = fminf(fmaxf(rintf(e[j] * inv), -127.f), 127.f);
            float r1 = fmaf(-d1, sn, e[j]);
            float d2 = fminf(fmaxf(rintf(r1 * inv2), -127.f), 127.f);
            float r2 = fmaf(-d2, s2, r1);
            float d3 = fminf(fmaxf(rintf(r2 * inv3), -127.f), 127.f);
            X1[j] = d1; X2[j] = d2; X3[j] = d3;
        }
        p1[i] = pack4(X1[0], X1[1], X1[2], X1[3]);
        p2[i] = pack4(X2[0], X2[1], X2[2], X2[3]);
        p3[i] = pack4(X3[0], X3[1], X3[2], X3[3]);
    }
    int8_t* base = g_Ad + (size_t)row * (3 * K_IN) + tid * 16;
    *(uint4*)(base)             = make_uint4(p1[0], p1[1], p1[2], p1[3]);
    *(uint4*)(base + K_IN)      = make_uint4(p2[0], p2[1], p2[2], p2[3]);
    *(uint4*)(base + 2 * K_IN)  = make_uint4(p3[0], p3[1], p3[2], p3[3]);
}

// ------- GEMM kernel 1: digits 1+2.  g_G = s*(sn*G1 + s2*G2) -------
// Reverse raster (free; keeps k1's G tail at low addresses for k2).
__global__ void __launch_bounds__(256) gemm_imma2() {
    __shared__ char sbuf[2][3][MATB];    // [stage][X1|X2|B] = 48 KB

    const int tid = threadIdx.x;
    const int wid = tid >> 5;
    const int lane = tid & 31;
    const int wm = wid & 1;
    const int wn = wid >> 1;

    const int cid = (MT * NT - 1) - blockIdx.x;
    const int sup = cid >> 8;
    const int rem = cid & 255;
    const int tm = ((sup & 3) << 4) | (rem & 15);
    const int tn = ((sup >> 2) << 4) | (rem >> 4);

    int acc1[4][4][4], acc2[4][4][4];
    #pragma unroll
    for (int a = 0; a < 4; a++)
        #pragma unroll
        for (int b = 0; b < 4; b++)
            #pragma unroll
            for (int c = 0; c < 4; c++) { acc1[a][b][c] = 0; acc2[a][b][c] = 0; }

    const char* gsrc[6];
    uint32_t doff[6];
    #pragma unroll
    for (int j = 0; j < 6; j++) {
        int id = j * 256 + tid;
        int mat = id >> 9;           // 0=X1, 1=X2, 2=B
        int r2 = id & 511;
        int row = r2 >> 2;
        int c16 = r2 & 3;
        if (mat == 0)
            gsrc[j] = (const char*)g_Ad + (size_t)(tm * BM + row) * (3 * K_IN) + c16 * 16;
        else if (mat == 1)
            gsrc[j] = (const char*)g_Ad + (size_t)(tm * BM + row) * (3 * K_IN) + K_IN + c16 * 16;
        else
            gsrc[j] = (const char*)g_Bq + (size_t)(tn * BN + row) * K_IN + c16 * 16;
        doff[j] = (uint32_t)(mat * MATB + row * 64 + SWZ(row, c16));
    }
    const uint32_t base_u[2] = { smem_u32(sbuf[0]), smem_u32(sbuf[1]) };

    #pragma unroll
    for (int j = 0; j < 6; j++) CP_ASYNC16(base_u[0] + doff[j], gsrc[j]);
    CP_COMMIT();

    for (int i = 0; i < NCH; i++) {
        const int b = i & 1;
        if (i + 1 < NCH) {
            const int nb = (i + 1) & 1;
            const size_t ko = (size_t)(i + 1) * BKB;
            #pragma unroll
            for (int j = 0; j < 6; j++)
                CP_ASYNC16(base_u[nb] + doff[j], gsrc[j] + ko);
            CP_COMMIT();
            CP_WAIT1();
        } else {
            CP_WAIT0();
        }
        __syncthreads();

        const uint32_t sA1 = base_u[b];
        const uint32_t sA2 = base_u[b] + MATB;
        const uint32_t sB  = base_u[b] + 2 * MATB;

        #pragma unroll
        for (int ks = 0; ks < 2; ks++) {
            uint32_t bf[4][2];
            #pragma unroll
            for (int g = 0; g < 2; g++) {
                const int brow = wn * 32 + g * 16 + ((lane >> 4) << 3) + (lane & 7);
                const int bc16 = ks * 2 + ((lane >> 3) & 1);
                uint32_t r[4];
                ldm_x4(r, sB + (uint32_t)(brow * 64 + SWZ(brow, bc16)));
                bf[2 * g][0] = r[0]; bf[2 * g][1] = r[1];
                bf[2 * g + 1][0] = r[2]; bf[2 * g + 1][1] = r[3];
            }
            #pragma unroll
            for (int mt = 0; mt < 4; mt++) {
                const int arow = wm * 64 + mt * 16 + (lane & 15);
                const int ac16 = ks * 2 + (lane >> 4);
                const uint32_t aoff = (uint32_t)(arow * 64 + SWZ(arow, ac16));
                uint32_t a1[4], a2[4];
                ldm_x4(a1, sA1 + aoff);
                ldm_x4(a2, sA2 + aoff);
                #pragma unroll
                for (int nt = 0; nt < 4; nt++) {
                    imma(acc1[mt][nt], a1, bf[nt][0], bf[nt][1]);
                    imma(acc2[mt][nt], a2, bf[nt][0], bf[nt][1]);
                }
            }
        }
        __syncthreads();
    }

    // epilogue: g_G = s*sn*G1 + s*s2*G2
    const float s = g_scale;
    const int rbase = tm * BM + wm * 64 + (lane >> 2);
    const int cbase = tn * BN + wn * 32 + 2 * (lane & 3);
    #pragma unroll
    for (int mt = 0; mt < 4; mt++) {
        const int r0 = rbase + mt * 16;
        const int r1 = r0 + 8;
        const float f10 = s * g_sn[r0];
        const float f20 = f10 * INV254;
        const float f11 = s * g_sn[r1];
        const float f21 = f11 * INV254;
        #pragma unroll
        for (int nt = 0; nt < 4; nt++) {
            const int cc = cbase + nt * 8;
            float2 v0, v1;
            v0.x = fmaf(f10, (float)acc1[mt][nt][0], f20 * (float)acc2[mt][nt][0]);
            v0.y = fmaf(f10, (float)acc1[mt][nt][1], f20 * (float)acc2[mt][nt][1]);
            v1.x = fmaf(f11, (float)acc1[mt][nt][2], f21 * (float)acc2[mt][nt][2]);
            v1.y = fmaf(f11, (float)acc1[mt][nt][3], f21 * (float)acc2[mt][nt][3]);
            *(float2*)&g_G[(size_t)r0 * FOUT + cc] = v0;
            *(float2*)&g_G[(size_t)r1 * FOUT + cc] = v1;
        }
    }
}

// ------- GEMM kernel 2: digit 3.  g_G += s*s3*G3; fused BN stats partials -------
__global__ void __launch_bounds__(256) gemm_imma1() {
    __shared__ char sbuf[2][2][MATB];    // [stage][X3|B] = 32 KB
    __shared__ float red[8][4][16];      // cross-warp stats reduction (2 KB)

    const int tid = threadIdx.x;
    const int wid = tid >> 5;
    const int lane = tid & 31;
    const int wm = wid & 1;
    const int wn = wid >> 1;

    const int cid = blockIdx.x;
    const int sup = cid >> 8;
    const int rem = cid & 255;
    const int tm = ((sup & 3) << 4) | (rem & 15);
    const int tn = ((sup >> 2) << 4) | (rem >> 4);

    int acc3[4][4][4];
    #pragma unroll
    for (int a = 0; a < 4; a++)
        #pragma unroll
        for (int b = 0; b < 4; b++)
            #pragma unroll
            for (int c = 0; c < 4; c++) acc3[a][b][c] = 0;

    const char* gsrc[4];
    uint32_t doff[4];
    #pragma unroll
    for (int j = 0; j < 4; j++) {
        int id = j * 256 + tid;
        int mat = id >> 9;           // 0=X3, 1=B
        int r2 = id & 511;
        int row = r2 >> 2;
        int c16 = r2 & 3;
        if (mat == 0)
            gsrc[j] = (const char*)g_Ad + (size_t)(tm * BM + row) * (3 * K_IN) + 2 * K_IN + c16 * 16;
        else
            gsrc[j] = (const char*)g_Bq + (size_t)(tn * BN + row) * K_IN + c16 * 16;
        doff[j] = (uint32_t)(mat * MATB + row * 64 + SWZ(row, c16));
    }
    const uint32_t base_u[2] = { smem_u32(sbuf[0]), smem_u32(sbuf[1]) };

    #pragma unroll
    for (int j = 0; j < 4; j++) CP_ASYNC16(base_u[0] + doff[j], gsrc[j]);
    CP_COMMIT();

    for (int i = 0; i < NCH; i++) {
        const int b = i & 1;
        if (i + 1 < NCH) {
            const int nb = (i + 1) & 1;
            const size_t ko = (size_t)(i + 1) * BKB;
            #pragma unroll
            for (int j = 0; j < 4; j++)
                CP_ASYNC16(base_u[nb] + doff[j], gsrc[j] + ko);
            CP_COMMIT();
            CP_WAIT1();
        } else {
            CP_WAIT0();
        }
        __syncthreads();

        const uint32_t sA3 = base_u[b];
        const uint32_t sB  = base_u[b] + MATB;

        #pragma unroll
        for (int ks = 0; ks < 2; ks++) {
            uint32_t bf[4][2];
            #pragma unroll
            for (int g = 0; g < 2; g++) {
                const int brow = wn * 32 + g * 16 + ((lane >> 4) << 3) + (lane & 7);
                const int bc16 = ks * 2 + ((lane >> 3) & 1);
                uint32_t r[4];
                ldm_x4(r, sB + (uint32_t)(brow * 64 + SWZ(brow, bc16)));
                bf[2 * g][0] = r[0]; bf[2 * g][1] = r[1];
                bf[2 * g + 1][0] = r[2]; bf[2 * g + 1][1] = r[3];
            }
            #pragma unroll
            for (int mt = 0; mt < 4; mt++) {
                const int arow = wm * 64 + mt * 16 + (lane & 15);
                const int ac16 = ks * 2 + (lane >> 4);
                uint32_t a3[4];
                ldm_x4(a3, sA3 + (uint32_t)(arow * 64 + SWZ(arow, ac16)));
                #pragma unroll
                for (int nt = 0; nt < 4; nt++)
                    imma(acc3[mt][nt], a3, bf[nt][0], bf[nt][1]);
            }
        }
        __syncthreads();
    }

    // epilogue: g_G += s*s3*G3, with fused per-CTA column sum/sumsq
    const float s = g_scale;
    const int rbase = tm * BM + wm * 64 + (lane >> 2);
    const int cbase = tn * BN + wn * 32 + 2 * (lane & 3);
    float cs[4][2], cq[4][2];
    #pragma unroll
    for (int nt = 0; nt < 4; nt++) {
        cs[nt][0] = 0.f; cs[nt][1] = 0.f;
        cq[nt][0] = 0.f; cq[nt][1] = 0.f;
    }
    #pragma unroll
    for (int mt = 0; mt < 4; mt++) {
        const int r0 = rbase + mt * 16;
        const int r1 = r0 + 8;
        const float f30 = ((s * g_sn[r0]) * INV254) * INV254;
        const float f31 = ((s * g_sn[r1]) * INV254) * INV254;
        #pragma unroll
        for (int nt = 0; nt < 4; nt++) {
            const int cc = cbase + nt * 8;
            float2 v0 = *(float2*)&g_G[(size_t)r0 * FOUT + cc];
            float2 v1 = *(float2*)&g_G[(size_t)r1 * FOUT + cc];
            v0.x = fmaf(f30, (float)acc3[mt][nt][0], v0.x);
            v0.y = fmaf(f30, (float)acc3[mt][nt][1], v0.y);
            v1.x = fmaf(f31, (float)acc3[mt][nt][2], v1.x);
            v1.y = fmaf(f31, (float)acc3[mt][nt][3], v1.y);
            *(float2*)&g_G[(size_t)r0 * FOUT + cc] = v0;
            *(float2*)&g_G[(size_t)r1 * FOUT + cc] = v1;
            cs[nt][0] += v0.x + v1.x;   cs[nt][1] += v0.y + v1.y;
            cq[nt][0] = fmaf(v0.x, v0.x, fmaf(v1.x, v1.x, cq[nt][0]));
            cq[nt][1] = fmaf(v0.y, v0.y, fmaf(v1.y, v1.y, cq[nt][1]));
        }
    }
    #pragma unroll
    for (int o = 16; o >= 4; o >>= 1) {
        #pragma unroll
        for (int nt = 0; nt < 4; nt++) {
            cs[nt][0] += __shfl_down_sync(0xffffffffu, cs[nt][0], o);
            cs[nt][1] += __shfl_down_sync(0xffffffffu, cs[nt][1], o);
            cq[nt][0] += __shfl_down_sync(0xffffffffu, cq[nt][0], o);
            cq[nt][1] += __shfl_down_sync(0xffffffffu, cq[nt][1], o);
        }
    }
    if (lane < 4) {
        #pragma unroll
        for (int nt = 0; nt < 4; nt++) {
            red[wid][lane][nt * 2]     = cs[nt][0];
            red[wid][lane][nt * 2 + 1] = cs[nt][1];
            red[wid][lane][8 + nt * 2]     = cq[nt][0];
            red[wid][lane][8 + nt * 2 + 1] = cq[nt][1];
        }
    }
    __syncthreads();
    if (wm == 0 && lane < 4) {
        const int col0 = tn * BN + wn * 32 + 2 * lane;
        #pragma unroll
        for (int nt = 0; nt < 4; nt++) {
            #pragma unroll
            for (int h = 0; h < 2; h++) {
                float ssum = red[wid][lane][nt * 2 + h] + red[wid + 1][lane][nt * 2 + h];
                float qsum = red[wid][lane][8 + nt * 2 + h] + red[wid + 1][lane][8 + nt * 2 + h];
                g_psum2[tm][col0 + nt * 8 + h] = ssum;
                g_psq2[tm][col0 + nt * 8 + h] = qsum;
            }
        }
    }
}

// ---------------- coef + BN + act-quant ----------------
__global__ void coef_kernel(int Nr, int Nc) {
    int c = blockIdx.x * blockDim.x + threadIdx.x;
    if (c >= Nc) return;
    float s = 0.f, q = 0.f;
    #pragma unroll 8
    for (int i = 0; i < MT; i++) { s += g_psum2[i][c]; q += g_psq2[i][c]; }
    float mean = s / (float)Nr;
    float ex2  = q / (float)Nr;
    float var  = ex2 - mean * mean;
    g_mean[c] = mean;
    g_rstd[c] = (float)(1.0 / sqrt((double)var + 1e-5));
}

// Vectorized BN + activation quantization (float4), reverse traversal.
__global__ void bnq_kernel(const float* __restrict__ gamma,
                           const float* __restrict__ beta,
                           const int* __restrict__ abits,
                           float* __restrict__ out, int total4) {
    float na = (float)((1 << (*abits)) - 1);
    for (int i = blockIdx.x * blockDim.x + threadIdx.x; i < total4;
         i += gridDim.x * blockDim.x) {
        int j = total4 - 1 - i;
        int c = (j << 2) & (FOUT - 1);
        float4 g  = ((const float4*)g_G)[j];
        float4 ga = *(const float4*)&gamma[c];
        float4 be = *(const float4*)&beta[c];
        float4 mu = *(const float4*)&g_mean[c];
        float4 rs = *(const float4*)&g_rstd[c];
        float4 r;
        {
            float y = ga.x * (g.x - mu.x) * rs.x + be.x;
            float yc = fminf(fmaxf(y, 0.f), 1.f);
            r.x = yc + (__fdiv_rn(rintf(yc * na), na) - yc);
        }
        {
            float y = ga.y * (g.y - mu.y) * rs.y + be.y;
            float yc = fminf(fmaxf(y, 0.f), 1.f);
            r.y = yc + (__fdiv_rn(rintf(yc * na), na) - yc);
        }
        {
            float y = ga.z * (g.z - mu.z) * rs.z + be.z;
            float yc = fminf(fmaxf(y, 0.f), 1.f);
            r.z = yc + (__fdiv_rn(rintf(yc * na), na) - yc);
        }
        {
            float y = ga.w * (g.w - mu.w) * rs.w + be.w;
            float yc = fminf(fmaxf(y, 0.f), 1.f);
            r.w = yc + (__fdiv_rn(rintf(yc * na), na) - yc);
        }
        ((float4*)out)[j] = r;
    }
}

// ---------------- launch ----------------
extern "C" void kernel_launch(void* const* d_in, const int* in_sizes, int n_in,
                              void* d_out, int out_size) {
    const float* x     = (const float*)d_in[0];
    const float* W     = (const float*)d_in[1];
    const float* gamma = (const float*)d_in[2];
    const float* beta  = (const float*)d_in[3];
    const int*   wbits = (const int*)d_in[4];
    const int*   abits = (const int*)d_in[5];

    maxabs_kernel<<<256, 256>>>(W, FOUT * K_IN);
    scale_kernel<<<1, 1>>>(wbits);
    quantm_kernel<<<(FOUT * K_IN / 16) / 256, 256>>>(W, wbits);
    rowdig_kernel<<<NROW, 256>>>(x);

    gemm_imma2<<<MT * NT, 256>>>();
    gemm_imma1<<<MT * NT, 256>>>();

    coef_kernel<<<(FOUT + 255) / 256, 256>>>(NROW, FOUT);
    bnq_kernel<<<2048, 256>>>(gamma, beta, abits, (float*)d_out,
                              NROW * FOUT / 4);
}